// round 4
// baseline (speedup 1.0000x reference)
#include <cuda_runtime.h>
#include <cstdint>

#define N_ 2
#define C_ 64
#define D_ 8
#define H_ 56
#define W_ 56
#define G_ 8
#define K_ 27
#define CO_OFF 648
#define P_ (D_*H_*W_)          // 25088
#define DP_ (D_+2)
#define HP_ (H_+2)
#define WP_ (W_+2)
#define PPAD_ (DP_*HP_*WP_)    // 33640
#define HPWP_ (HP_*WP_)

// ---------------- scratch (no allocation allowed) ----------------
__device__ float g_xpad[N_*C_*PPAD_];    // padded input for offset conv
__device__ float g_y2pad[N_*C_*PPAD_];   // padded bn1+relu output for conv2
__device__ float g_off[N_*CO_OFF*P_];    // offset tensor (130 MB)
__device__ float g_y1[N_*C_*P_];         // deform conv output
__device__ float g_y3[N_*C_*P_];         // conv2 output
__device__ float g_stats[4*C_];          // mean1, istd1, mean2, istd2

// ---------------- helpers ----------------
__device__ __forceinline__ uint32_t f2tf32(float x) {
    uint32_t r;
    asm("cvt.rna.tf32.f32 %0, %1;" : "=r"(r) : "f"(x));
    return r;
}

__device__ __forceinline__ void mma_tf32(float c[4], const uint32_t a[4],
                                         uint32_t b0, uint32_t b1) {
    asm volatile(
        "mma.sync.aligned.m16n8k8.row.col.f32.tf32.tf32.f32 "
        "{%0,%1,%2,%3}, {%4,%5,%6,%7}, {%8,%9}, {%0,%1,%2,%3};"
        : "+f"(c[0]), "+f"(c[1]), "+f"(c[2]), "+f"(c[3])
        : "r"(a[0]), "r"(a[1]), "r"(a[2]), "r"(a[3]), "r"(b0), "r"(b1));
}

// ---------------- kernel 0: build padded x, zero pad edges of y2pad ----------------
__global__ void padinit_kernel(const float* __restrict__ x) {
    int idx = blockIdx.x * 256 + threadIdx.x;
    if (idx >= N_*C_*PPAD_) return;
    int wp = idx % WP_;
    int hp = (idx / WP_) % HP_;
    int dp = (idx / (WP_*HP_)) % DP_;
    int nc = idx / PPAD_;
    bool interior = (dp >= 1 && dp <= D_ && hp >= 1 && hp <= H_ && wp >= 1 && wp <= W_);
    float v = 0.f;
    if (interior)
        v = x[nc * P_ + (dp-1) * (H_*W_) + (hp-1) * W_ + (wp-1)];
    g_xpad[idx] = v;
    if (!interior) g_y2pad[idx] = 0.f;
}

// ---------------- kernel 1: offset conv as tf32 implicit GEMM ----------
// BM=64 co x BN=224 positions (4 rows h..h+3 of one (n,d)). 256 thr, warps 2M x 4N.
// grid: (224, 11)
__global__ __launch_bounds__(256) void offconv_mma_kernel(const float* __restrict__ w_off,
                                                          const float* __restrict__ b_off) {
    __shared__ float Ws[64*36];     // weights [co][32k], stride 36
    __shared__ float slab[1044];    // xpad slab [kd 3][hh 6][ww 58]
    __shared__ int   lut[32];       // tap -> slab base offset

    int bx = blockIdx.x;
    int hq = bx % 14;
    int h  = hq * 4;
    int d  = (bx / 14) % D_;
    int n  = bx / (14 * D_);
    int cot = blockIdx.y;

    int tid  = threadIdx.x;
    int lane = tid & 31, warp = tid >> 5;
    int gid  = lane >> 2, tg = lane & 3;
    int mw   = warp >> 2, nw = warp & 3;

    if (tid < 32) {
        int j = tid, base = 0;
        if (j < 27) {
            int kd = j / 9, kh = (j / 3) % 3, kw = j % 3;
            base = kd * 348 + kh * 58 + kw;   // 348 = 6*58
        }
        lut[j] = base;
    }

    float c[2][7][4];
#pragma unroll
    for (int mt = 0; mt < 2; mt++)
#pragma unroll
        for (int nt = 0; nt < 7; nt++)
#pragma unroll
            for (int i = 0; i < 4; i++) c[mt][nt][i] = 0.f;

    const float* xp = g_xpad + n * (C_*PPAD_) + d * HPWP_ + h * WP_;

    for (int ci = 0; ci < C_; ci++) {
        __syncthreads();
        const float* wsrc = w_off + (size_t)ci * 27;
#pragma unroll
        for (int i = tid; i < 2048; i += 256) {
            int co = i >> 5, j = i & 31;
            int cog = cot * 64 + co;
            float v = 0.f;
            if (j < 27 && cog < CO_OFF) v = wsrc[(size_t)cog * 1728 + j];
            Ws[co * 36 + j] = __uint_as_float(f2tf32(v));
        }
        const float* src = xp + (size_t)ci * PPAD_;
#pragma unroll
        for (int i = tid; i < 1044; i += 256) {
            int kd = i / 348;
            int r2 = i - kd * 348;
            int hh = r2 / 58;
            int ww = r2 - hh * 58;
            slab[i] = __uint_as_float(f2tf32(src[kd * HPWP_ + hh * WP_ + ww]));
        }
        __syncthreads();

#pragma unroll
        for (int ks = 0; ks < 4; ks++) {
            int l0 = lut[ks * 8 + tg];
            int l1 = lut[ks * 8 + tg + 4];
            uint32_t a[2][4];
#pragma unroll
            for (int mt = 0; mt < 2; mt++) {
                const float* wr = &Ws[(mw * 32 + mt * 16 + gid) * 36 + ks * 8 + tg];
                a[mt][0] = __float_as_uint(wr[0]);
                a[mt][1] = __float_as_uint(wr[8 * 36]);
                a[mt][2] = __float_as_uint(wr[4]);
                a[mt][3] = __float_as_uint(wr[8 * 36 + 4]);
            }
            int ro = nw * 58 + gid;
#pragma unroll
            for (int nt = 0; nt < 7; nt++) {
                uint32_t b0 = __float_as_uint(slab[l0 + ro]);
                uint32_t b1 = __float_as_uint(slab[l1 + ro]);
                mma_tf32(c[0][nt], a[0], b0, b1);
                mma_tf32(c[1][nt], a[1], b0, b1);
                ro += 8;
            }
        }
    }

    int hrow = h + nw;
    int pbase = (d * H_ + hrow) * W_;
#pragma unroll
    for (int mt = 0; mt < 2; mt++) {
        int co0 = cot * 64 + mw * 32 + mt * 16 + gid;
#pragma unroll
        for (int half = 0; half < 2; half++) {
            int co = co0 + half * 8;
            if (co < CO_OFF) {
                float bo = b_off[co];
                float* outp = g_off + ((size_t)(n * CO_OFF + co)) * P_ + pbase;
#pragma unroll
                for (int nt = 0; nt < 7; nt++) {
                    int w0 = nt * 8 + tg * 2;
                    outp[w0]     = c[mt][nt][half * 2 + 0] + bo;
                    outp[w0 + 1] = c[mt][nt][half * 2 + 1] + bo;
                }
            }
        }
    }
}

// ---------------- kernel 2: deformable conv (sample + 3xtf32 MMA) ----------------
// grid: N*D*H   block: 256 (8 warps; warps 0-6 do MMA over 8 columns each)
__global__ __launch_bounds__(256) void deform_kernel(const float* __restrict__ x,
                                                     const float* __restrict__ w1) {
    int ndh = blockIdx.x;
    int h = ndh % H_;
    int d = (ndh / H_) % D_;
    int n = ndh / (D_*H_);
    int tid  = threadIdx.x;
    int lane = tid & 31, warp = tid >> 5;
    int gid  = lane >> 2, tg = lane & 3;

    __shared__ float svalsH[8*56];      // [cl][w] stride 56 (bank-perfect B frags)
    __shared__ float svalsL[8*56];
    __shared__ float wsmH[2][64*12];    // [o][cl] stride 12 (bank-perfect A frags)
    __shared__ float wsmL[2][64*12];
    __shared__ int   clin[2][56*9];
    __shared__ float cwgt[2][56*9];

    float c[4][4];
#pragma unroll
    for (int mt = 0; mt < 4; mt++)
#pragma unroll
        for (int i = 0; i < 4; i++) c[mt][i] = 0.f;

    const float* xn = x + n * (C_*P_);

    // phaseA: threads 0-55 corner math; threads 56-255 stage w1 slice hi/lo
    auto phaseA = [&](int t, int buf) {
        int g = t / 27, k = t - g * 27;
        if (tid < 56) {
            int w = tid;
            int kd = k / 9, kh = (k / 3) % 3, kw = k % 3;
            int obase = (n * CO_OFF + (g*K_ + k) * 3) * P_ + (d * H_ + h) * W_ + w;
            float od = __ldg(&g_off[obase]);
            float oh = __ldg(&g_off[obase + P_]);
            float ow = __ldg(&g_off[obase + 2*P_]);
            float pd = (float)(d + kd - 1) + od;
            float ph = (float)(h + kh - 1) + oh;
            float pw = (float)(w + kw - 1) + ow;
            float d0f = floorf(pd), h0f = floorf(ph), w0f = floorf(pw);
            float fd = pd - d0f, fh = ph - h0f, fw = pw - w0f;
            int d0 = (int)d0f, h0 = (int)h0f, w0 = (int)w0f;
#pragma unroll
            for (int c8 = 0; c8 < 8; c8++) {
                int cd = c8 >> 2, ch = (c8 >> 1) & 1, cw = c8 & 1;
                int id = d0 + cd, ih = h0 + ch, iw = w0 + cw;
                float wt = (cd ? fd : 1.f - fd) * (ch ? fh : 1.f - fh) * (cw ? fw : 1.f - fw);
                bool valid = (id >= 0 && id < D_ && ih >= 0 && ih < H_ && iw >= 0 && iw < W_);
                int idc = min(max(id, 0), D_-1);
                int ihc = min(max(ih, 0), H_-1);
                int iwc = min(max(iw, 0), W_-1);
                clin[buf][w*9 + c8] = (idc * H_ + ihc) * W_ + iwc;
                cwgt[buf][w*9 + c8] = valid ? wt : 0.f;
            }
        } else {
            for (int i = tid - 56; i < 512; i += 200) {
                int o = i >> 3, cl = i & 7;
                float v = __ldg(&w1[(o * C_ + g*8 + cl) * K_ + k]);
                uint32_t hi = f2tf32(v);
                float lo = v - __uint_as_float(hi);
                wsmH[buf][o*12 + cl] = __uint_as_float(hi);
                wsmL[buf][o*12 + cl] = __uint_as_float(f2tf32(lo));
            }
        }
    };

    phaseA(0, 0);
    __syncthreads();

    for (int t = 0; t < 216; t++) {
        int buf = t & 1;
        int g = t / 27;
        // --- trilinear sampling (448 values over 256 threads), hi/lo split ---
#pragma unroll
        for (int rep = 0; rep < 2; rep++) {
            int i = tid + rep * 256;
            if (i < 448) {
                int cl = i / 56, w = i - cl * 56;
                const float* xc = xn + (g*8 + cl) * P_;
                const int*   ip = &clin[buf][w*9];
                const float* wp = &cwgt[buf][w*9];
                float s = 0.f;
#pragma unroll
                for (int c8 = 0; c8 < 8; c8++)
                    s += __ldg(&xc[ip[c8]]) * wp[c8];
                uint32_t hi = f2tf32(s);
                float lo = s - __uint_as_float(hi);
                svalsH[cl*56 + w] = __uint_as_float(hi);
                svalsL[cl*56 + w] = __uint_as_float(f2tf32(lo));
            }
        }
        __syncthreads();
        // --- stage next tap (overlaps with MMA below) ---
        if (t + 1 < 216) phaseA(t + 1, buf ^ 1);
        // --- MMA accumulate: warps 0-6, 8 columns each, k=8 (cl), M=64 ---
        if (warp < 7) {
            int col = warp * 8 + gid;
            uint32_t b0H = __float_as_uint(svalsH[tg*56 + col]);
            uint32_t b1H = __float_as_uint(svalsH[(tg+4)*56 + col]);
            uint32_t b0L = __float_as_uint(svalsL[tg*56 + col]);
            uint32_t b1L = __float_as_uint(svalsL[(tg+4)*56 + col]);
#pragma unroll
            for (int mt = 0; mt < 4; mt++) {
                int r0 = (mt*16 + gid) * 12 + tg;
                uint32_t aH[4], aL[4];
                aH[0] = __float_as_uint(wsmH[buf][r0]);
                aH[1] = __float_as_uint(wsmH[buf][r0 + 96]);      // +8 rows
                aH[2] = __float_as_uint(wsmH[buf][r0 + 4]);
                aH[3] = __float_as_uint(wsmH[buf][r0 + 100]);
                aL[0] = __float_as_uint(wsmL[buf][r0]);
                aL[1] = __float_as_uint(wsmL[buf][r0 + 96]);
                aL[2] = __float_as_uint(wsmL[buf][r0 + 4]);
                aL[3] = __float_as_uint(wsmL[buf][r0 + 100]);
                mma_tf32(c[mt], aH, b0H, b1H);
                mma_tf32(c[mt], aH, b0L, b1L);
                mma_tf32(c[mt], aL, b0H, b1H);
            }
        }
        __syncthreads();
    }

    // epilogue: warp w<7 owns columns w*8..w*8+7
    if (warp < 7) {
        int pbase = (d * H_ + h) * W_ + warp * 8 + tg * 2;
#pragma unroll
        for (int mt = 0; mt < 4; mt++) {
#pragma unroll
            for (int half = 0; half < 2; half++) {
                int o = mt*16 + gid + half*8;
                float* outp = g_y1 + ((size_t)(n * C_ + o)) * P_ + pbase;
                outp[0] = c[mt][half*2 + 0];
                outp[1] = c[mt][half*2 + 1];
            }
        }
    }
}

// ---------------- BN statistics (deterministic, one block per channel) ----------------
__global__ void bnstats_kernel(int which) {
    const float* y = which ? g_y3 : g_y1;
    int c = blockIdx.x;
    int tid = threadIdx.x;
    float s = 0.f, s2 = 0.f;
    for (int n = 0; n < N_; n++) {
        const float* p = y + (n * C_ + c) * P_;
        for (int i = tid; i < P_; i += 256) {
            float v = p[i];
            s += v; s2 += v * v;
        }
    }
    __shared__ float rs[256], rq[256];
    rs[tid] = s; rq[tid] = s2;
    __syncthreads();
    for (int st = 128; st > 0; st >>= 1) {
        if (tid < st) { rs[tid] += rs[tid+st]; rq[tid] += rq[tid+st]; }
        __syncthreads();
    }
    if (tid == 0) {
        float cnt = (float)(N_ * P_);
        float m = rs[0] / cnt;
        float var = rq[0] / cnt - m * m;
        g_stats[which*128 + c]      = m;
        g_stats[which*128 + 64 + c] = rsqrtf(var + 1e-5f);
    }
}

// ---------------- BN1 apply + relu -> padded buffer for conv2 ----------------
__global__ void bnrelu_kernel(const float* __restrict__ gamma, const float* __restrict__ beta) {
    int idx = blockIdx.x * 256 + threadIdx.x;
    if (idx >= N_*C_*P_) return;
    int c = (idx / P_) % C_;
    float m = g_stats[c], is = g_stats[64 + c];
    float v = (g_y1[idx] - m) * is * gamma[c] + beta[c];
    v = fmaxf(v, 0.f);
    int pp = idx % P_;
    int w = pp % W_, hh = (pp / W_) % H_, dd = pp / (W_*H_);
    int nc = idx / P_;
    g_y2pad[nc * PPAD_ + (dd+1) * (HP_*WP_) + (hh+1) * WP_ + (w+1)] = v;
}

// ---------------- kernel 5: conv2 as 3xtf32 implicit GEMM -------
__global__ __launch_bounds__(256) void conv2_mma_kernel(const float* __restrict__ w2,
                                                        const float* __restrict__ b2) {
    __shared__ float WsH[64*36];
    __shared__ float WsL[64*36];
    __shared__ float slabH[1044];
    __shared__ float slabL[1044];
    __shared__ int   lut[32];

    int bx = blockIdx.x;
    int hq = bx % 14;
    int h  = hq * 4;
    int d  = (bx / 14) % D_;
    int n  = bx / (14 * D_);

    int tid  = threadIdx.x;
    int lane = tid & 31, warp = tid >> 5;
    int gid  = lane >> 2, tg = lane & 3;
    int mw   = warp >> 2, nw = warp & 3;

    if (tid < 32) {
        int j = tid, base = 0;
        if (j < 27) {
            int kd = j / 9, kh = (j / 3) % 3, kw = j % 3;
            base = kd * 348 + kh * 58 + kw;
        }
        lut[j] = base;
    }

    float c[2][7][4];
#pragma unroll
    for (int mt = 0; mt < 2; mt++)
#pragma unroll
        for (int nt = 0; nt < 7; nt++)
#pragma unroll
            for (int i = 0; i < 4; i++) c[mt][nt][i] = 0.f;

    const float* xp = g_y2pad + n * (C_*PPAD_) + d * HPWP_ + h * WP_;

    for (int ci = 0; ci < C_; ci++) {
        __syncthreads();
        const float* wsrc = w2 + (size_t)ci * 27;
#pragma unroll
        for (int i = tid; i < 2048; i += 256) {
            int co = i >> 5, j = i & 31;
            float v = 0.f;
            if (j < 27) v = wsrc[(size_t)co * 1728 + j];
            uint32_t hi = f2tf32(v);
            float lo = v - __uint_as_float(hi);
            WsH[co * 36 + j] = __uint_as_float(hi);
            WsL[co * 36 + j] = __uint_as_float(f2tf32(lo));
        }
        const float* src = xp + (size_t)ci * PPAD_;
#pragma unroll
        for (int i = tid; i < 1044; i += 256) {
            int kd = i / 348;
            int r2 = i - kd * 348;
            int hh = r2 / 58;
            int ww = r2 - hh * 58;
            float v = src[kd * HPWP_ + hh * WP_ + ww];
            uint32_t hi = f2tf32(v);
            float lo = v - __uint_as_float(hi);
            slabH[i] = __uint_as_float(hi);
            slabL[i] = __uint_as_float(f2tf32(lo));
        }
        __syncthreads();

#pragma unroll
        for (int ks = 0; ks < 4; ks++) {
            int l0 = lut[ks * 8 + tg];
            int l1 = lut[ks * 8 + tg + 4];
            uint32_t aH[2][4], aL[2][4];
#pragma unroll
            for (int mt = 0; mt < 2; mt++) {
                int rbase = (mw * 32 + mt * 16 + gid) * 36 + ks * 8 + tg;
                aH[mt][0] = __float_as_uint(WsH[rbase]);
                aH[mt][1] = __float_as_uint(WsH[rbase + 8*36]);
                aH[mt][2] = __float_as_uint(WsH[rbase + 4]);
                aH[mt][3] = __float_as_uint(WsH[rbase + 8*36 + 4]);
                aL[mt][0] = __float_as_uint(WsL[rbase]);
                aL[mt][1] = __float_as_uint(WsL[rbase + 8*36]);
                aL[mt][2] = __float_as_uint(WsL[rbase + 4]);
                aL[mt][3] = __float_as_uint(WsL[rbase + 8*36 + 4]);
            }
            int ro = nw * 58 + gid;
#pragma unroll
            for (int nt = 0; nt < 7; nt++) {
                uint32_t bH0 = __float_as_uint(slabH[l0 + ro]);
                uint32_t bH1 = __float_as_uint(slabH[l1 + ro]);
                uint32_t bL0 = __float_as_uint(slabL[l0 + ro]);
                uint32_t bL1 = __float_as_uint(slabL[l1 + ro]);
#pragma unroll
                for (int mt = 0; mt < 2; mt++) {
                    mma_tf32(c[mt][nt], aH[mt], bH0, bH1);
                    mma_tf32(c[mt][nt], aH[mt], bL0, bL1);
                    mma_tf32(c[mt][nt], aL[mt], bH0, bH1);
                }
                ro += 8;
            }
        }
    }

    int hrow = h + nw;
    int pbase = (d * H_ + hrow) * W_;
#pragma unroll
    for (int mt = 0; mt < 2; mt++) {
        int co0 = mw * 32 + mt * 16 + gid;
#pragma unroll
        for (int half = 0; half < 2; half++) {
            int co = co0 + half * 8;
            float bo = b2[co];
            float* outp = g_y3 + ((size_t)(n * C_ + co)) * P_ + pbase;
#pragma unroll
            for (int nt = 0; nt < 7; nt++) {
                int w0 = nt * 8 + tg * 2;
                outp[w0]     = c[mt][nt][half * 2 + 0] + bo;
                outp[w0 + 1] = c[mt][nt][half * 2 + 1] + bo;
            }
        }
    }
}

// ---------------- final: bn2 + residual + relu ----------------
__global__ void final_kernel(const float* __restrict__ x,
                             const float* __restrict__ gamma2,
                             const float* __restrict__ beta2,
                             float* __restrict__ out) {
    int idx = blockIdx.x * 256 + threadIdx.x;
    if (idx >= N_*C_*P_) return;
    int c = (idx / P_) % C_;
    float m = g_stats[128 + c], is = g_stats[192 + c];
    float v = (g_y3[idx] - m) * is * gamma2[c] + beta2[c] + x[idx];
    out[idx] = fmaxf(v, 0.f);
}

// ---------------- launcher ----------------
extern "C" void kernel_launch(void* const* d_in, const int* in_sizes, int n_in,
                              void* d_out, int out_size) {
    const float* x      = (const float*)d_in[0];
    const float* w_off  = (const float*)d_in[1];
    const float* b_off  = (const float*)d_in[2];
    const float* w1     = (const float*)d_in[3];
    const float* gamma1 = (const float*)d_in[4];
    const float* beta1  = (const float*)d_in[5];
    const float* w2     = (const float*)d_in[6];
    const float* b2     = (const float*)d_in[7];
    const float* gamma2 = (const float*)d_in[8];
    const float* beta2  = (const float*)d_in[9];
    float* out = (float*)d_out;

    int padtot = N_*C_*PPAD_;
    int tot = N_*C_*P_;

    padinit_kernel<<<(padtot + 255) / 256, 256>>>(x);
    offconv_mma_kernel<<<dim3(224, 11), 256>>>(w_off, b_off);
    deform_kernel<<<N_*D_*H_, 256>>>(x, w1);
    bnstats_kernel<<<64, 256>>>(0);
    bnrelu_kernel<<<(tot + 255) / 256, 256>>>(gamma1, beta1);
    conv2_mma_kernel<<<224, 256>>>(w2, b2);
    bnstats_kernel<<<64, 256>>>(1);
    final_kernel<<<(tot + 255) / 256, 256>>>(x, gamma2, beta2, out);
}

// round 5
// speedup vs baseline: 1.3909x; 1.3909x over previous
#include <cuda_runtime.h>
#include <cstdint>

#define N_ 2
#define C_ 64
#define D_ 8
#define H_ 56
#define W_ 56
#define G_ 8
#define K_ 27
#define CO_OFF 648
#define P_ (D_*H_*W_)          // 25088
#define DP_ (D_+2)
#define HP_ (H_+2)
#define WP_ (W_+2)
#define PPAD_ (DP_*HP_*WP_)    // 33640
#define HPWP_ (HP_*WP_)

// ---------------- scratch (no allocation allowed) ----------------
__device__ float g_xpad[N_*C_*PPAD_];    // padded input for offset conv
__device__ float g_y2pad[N_*C_*PPAD_];   // padded bn1+relu output for conv2
__device__ float g_off[N_*CO_OFF*P_];    // offset tensor (130 MB)
__device__ float g_vals[N_*G_*K_*8*P_];  // sampled values (347 MB)
__device__ float g_y1[N_*C_*P_];         // deform conv output
__device__ float g_y3[N_*C_*P_];         // conv2 output
__device__ float g_stats[4*C_];          // mean1, istd1, mean2, istd2

// ---------------- helpers ----------------
__device__ __forceinline__ uint32_t f2tf32(float x) {
    uint32_t r;
    asm("cvt.rna.tf32.f32 %0, %1;" : "=r"(r) : "f"(x));
    return r;
}

__device__ __forceinline__ void mma_tf32(float c[4], const uint32_t a[4],
                                         uint32_t b0, uint32_t b1) {
    asm volatile(
        "mma.sync.aligned.m16n8k8.row.col.f32.tf32.tf32.f32 "
        "{%0,%1,%2,%3}, {%4,%5,%6,%7}, {%8,%9}, {%0,%1,%2,%3};"
        : "+f"(c[0]), "+f"(c[1]), "+f"(c[2]), "+f"(c[3])
        : "r"(a[0]), "r"(a[1]), "r"(a[2]), "r"(a[3]), "r"(b0), "r"(b1));
}

// ---------------- kernel 0: build padded x, zero pad edges of y2pad ----------------
__global__ void padinit_kernel(const float* __restrict__ x) {
    int idx = blockIdx.x * 256 + threadIdx.x;
    if (idx >= N_*C_*PPAD_) return;
    int wp = idx % WP_;
    int hp = (idx / WP_) % HP_;
    int dp = (idx / (WP_*HP_)) % DP_;
    int nc = idx / PPAD_;
    bool interior = (dp >= 1 && dp <= D_ && hp >= 1 && hp <= H_ && wp >= 1 && wp <= W_);
    float v = 0.f;
    if (interior)
        v = x[nc * P_ + (dp-1) * (H_*W_) + (hp-1) * W_ + (wp-1)];
    g_xpad[idx] = v;
    if (!interior) g_y2pad[idx] = 0.f;
}

// ---------------- kernel 1: offset conv as tf32 implicit GEMM ----------
// BM=64 co x BN=224 positions (4 rows h..h+3 of one (n,d)). 256 thr, warps 2M x 4N.
// grid: (224, 11)
__global__ __launch_bounds__(256) void offconv_mma_kernel(const float* __restrict__ w_off,
                                                          const float* __restrict__ b_off) {
    __shared__ float Ws[64*36];     // weights [co][32k], stride 36
    __shared__ float slab[1044];    // xpad slab [kd 3][hh 6][ww 58]
    __shared__ int   lut[32];       // tap -> slab base offset

    int bx = blockIdx.x;
    int hq = bx % 14;
    int h  = hq * 4;
    int d  = (bx / 14) % D_;
    int n  = bx / (14 * D_);
    int cot = blockIdx.y;

    int tid  = threadIdx.x;
    int lane = tid & 31, warp = tid >> 5;
    int gid  = lane >> 2, tg = lane & 3;
    int mw   = warp >> 2, nw = warp & 3;

    if (tid < 32) {
        int j = tid, base = 0;
        if (j < 27) {
            int kd = j / 9, kh = (j / 3) % 3, kw = j % 3;
            base = kd * 348 + kh * 58 + kw;   // 348 = 6*58
        }
        lut[j] = base;
    }

    float c[2][7][4];
#pragma unroll
    for (int mt = 0; mt < 2; mt++)
#pragma unroll
        for (int nt = 0; nt < 7; nt++)
#pragma unroll
            for (int i = 0; i < 4; i++) c[mt][nt][i] = 0.f;

    const float* xp = g_xpad + n * (C_*PPAD_) + d * HPWP_ + h * WP_;

    for (int ci = 0; ci < C_; ci++) {
        __syncthreads();
        const float* wsrc = w_off + (size_t)ci * 27;
#pragma unroll
        for (int i = tid; i < 2048; i += 256) {
            int co = i >> 5, j = i & 31;
            int cog = cot * 64 + co;
            float v = 0.f;
            if (j < 27 && cog < CO_OFF) v = wsrc[(size_t)cog * 1728 + j];
            Ws[co * 36 + j] = __uint_as_float(f2tf32(v));
        }
        const float* src = xp + (size_t)ci * PPAD_;
#pragma unroll
        for (int i = tid; i < 1044; i += 256) {
            int kd = i / 348;
            int r2 = i - kd * 348;
            int hh = r2 / 58;
            int ww = r2 - hh * 58;
            slab[i] = __uint_as_float(f2tf32(src[kd * HPWP_ + hh * WP_ + ww]));
        }
        __syncthreads();

#pragma unroll
        for (int ks = 0; ks < 4; ks++) {
            int l0 = lut[ks * 8 + tg];
            int l1 = lut[ks * 8 + tg + 4];
            uint32_t a[2][4];
#pragma unroll
            for (int mt = 0; mt < 2; mt++) {
                const float* wr = &Ws[(mw * 32 + mt * 16 + gid) * 36 + ks * 8 + tg];
                a[mt][0] = __float_as_uint(wr[0]);
                a[mt][1] = __float_as_uint(wr[8 * 36]);
                a[mt][2] = __float_as_uint(wr[4]);
                a[mt][3] = __float_as_uint(wr[8 * 36 + 4]);
            }
            int ro = nw * 58 + gid;
#pragma unroll
            for (int nt = 0; nt < 7; nt++) {
                uint32_t b0 = __float_as_uint(slab[l0 + ro]);
                uint32_t b1 = __float_as_uint(slab[l1 + ro]);
                mma_tf32(c[0][nt], a[0], b0, b1);
                mma_tf32(c[1][nt], a[1], b0, b1);
                ro += 8;
            }
        }
    }

    int hrow = h + nw;
    int pbase = (d * H_ + hrow) * W_;
#pragma unroll
    for (int mt = 0; mt < 2; mt++) {
        int co0 = cot * 64 + mw * 32 + mt * 16 + gid;
#pragma unroll
        for (int half = 0; half < 2; half++) {
            int co = co0 + half * 8;
            if (co < CO_OFF) {
                float bo = b_off[co];
                float* outp = g_off + ((size_t)(n * CO_OFF + co)) * P_ + pbase;
#pragma unroll
                for (int nt = 0; nt < 7; nt++) {
                    int w0 = nt * 8 + tg * 2;
                    outp[w0]     = c[mt][nt][half * 2 + 0] + bo;
                    outp[w0 + 1] = c[mt][nt][half * 2 + 1] + bo;
                }
            }
        }
    }
}

// ---------------- kernel 2a: deform gather (barrier-free, one thread per (n,g,k,p)) ----
// grid: N*G*K*98 blocks of 256 (98 = 25088/256)
__global__ __launch_bounds__(256) void deform_gather_kernel(const float* __restrict__ x) {
    int bx = blockIdx.x;
    int pc = bx % 98;
    int ngk = bx / 98;
    int k = ngk % K_;
    int g = (ngk / K_) % G_;
    int n = ngk / (K_ * G_);
    int p = pc * 256 + threadIdx.x;

    int w = p % W_;
    int h = (p / W_) % H_;
    int d = p / (W_ * H_);

    int kd = k / 9, kh = (k / 3) % 3, kw = k % 3;
    size_t obase = ((size_t)(n * CO_OFF + (g*K_ + k) * 3)) * P_ + p;
    float od = __ldg(&g_off[obase]);
    float oh = __ldg(&g_off[obase + P_]);
    float ow = __ldg(&g_off[obase + 2*(size_t)P_]);

    float pd = (float)(d + kd - 1) + od;
    float ph = (float)(h + kh - 1) + oh;
    float pw = (float)(w + kw - 1) + ow;
    float d0f = floorf(pd), h0f = floorf(ph), w0f = floorf(pw);
    float fd = pd - d0f, fh = ph - h0f, fw = pw - w0f;
    int d0 = (int)d0f, h0 = (int)h0f, w0 = (int)w0f;

    int   clin[8];
    float cwgt[8];
#pragma unroll
    for (int c8 = 0; c8 < 8; c8++) {
        int cd = c8 >> 2, ch = (c8 >> 1) & 1, cw = c8 & 1;
        int id = d0 + cd, ih = h0 + ch, iw = w0 + cw;
        float wt = (cd ? fd : 1.f - fd) * (ch ? fh : 1.f - fh) * (cw ? fw : 1.f - fw);
        bool valid = (id >= 0 && id < D_ && ih >= 0 && ih < H_ && iw >= 0 && iw < W_);
        int idc = min(max(id, 0), D_-1);
        int ihc = min(max(ih, 0), H_-1);
        int iwc = min(max(iw, 0), W_-1);
        clin[c8] = (idc * H_ + ihc) * W_ + iwc;
        cwgt[c8] = valid ? wt : 0.f;
    }

    const float* xg = x + ((size_t)(n * C_ + g * 8)) * P_;
    float* vout = g_vals + ((size_t)(((n * G_ + g) * K_ + k) * 8)) * P_ + p;
#pragma unroll
    for (int cl = 0; cl < 8; cl++) {
        const float* xc = xg + (size_t)cl * P_;
        float s = 0.f;
#pragma unroll
        for (int c8 = 0; c8 < 8; c8++)
            s += __ldg(&xc[clin[c8]]) * cwgt[c8];
        vout[(size_t)cl * P_] = s;
    }
}

// ---------------- kernel 2b: deform GEMM  y1[64,P] = w1[64x1728] x vals (3xtf32) -----
// BM=64 x BN=112 (rows h,h+1 of one (n,d)). 128 thr, warps 2M x 2N. grid: 448
__global__ __launch_bounds__(128) void deform_gemm_kernel(const float* __restrict__ w1) {
    __shared__ float WsH[64*12];    // [o][cl] stride 12
    __shared__ float WsL[64*12];
    __shared__ float BsH[8*120];    // [cl][pos] stride 120
    __shared__ float BsL[8*120];

    int bx = blockIdx.x;
    int hq = bx % 28;
    int h  = hq * 2;
    int d  = (bx / 28) % D_;
    int n  = bx / (28 * D_);

    int tid  = threadIdx.x;
    int lane = tid & 31, warp = tid >> 5;
    int gid  = lane >> 2, tg = lane & 3;
    int mw   = warp >> 1, nw = warp & 1;

    float c[2][7][4];
#pragma unroll
    for (int mt = 0; mt < 2; mt++)
#pragma unroll
        for (int nt = 0; nt < 7; nt++)
#pragma unroll
            for (int i = 0; i < 4; i++) c[mt][nt][i] = 0.f;

    int pbase = (d * H_ + h) * W_;

    for (int t = 0; t < 216; t++) {
        int g = t / 27, k = t - g * 27;
        __syncthreads();
        // stage A: w1[o][g*8+cl][k], hi/lo
#pragma unroll
        for (int i = tid; i < 512; i += 128) {
            int o = i >> 3, cl = i & 7;
            float v = __ldg(&w1[(o * C_ + g*8 + cl) * K_ + k]);
            uint32_t hi = f2tf32(v);
            float lo = v - __uint_as_float(hi);
            WsH[o*12 + cl] = __uint_as_float(hi);
            WsL[o*12 + cl] = __uint_as_float(f2tf32(lo));
        }
        // stage B: vals[(n,g,k,cl)][pbase + 0..111], hi/lo
        const float* vsrc = g_vals + ((size_t)(((n * G_ + g) * K_ + k) * 8)) * P_ + pbase;
#pragma unroll
        for (int i = tid; i < 896; i += 128) {
            int cl = i / 112, pp = i - cl * 112;
            float v = __ldg(&vsrc[(size_t)cl * P_ + pp]);
            uint32_t hi = f2tf32(v);
            float lo = v - __uint_as_float(hi);
            BsH[cl*120 + pp] = __uint_as_float(hi);
            BsL[cl*120 + pp] = __uint_as_float(f2tf32(lo));
        }
        __syncthreads();

        uint32_t aH[2][4], aL[2][4];
#pragma unroll
        for (int mt = 0; mt < 2; mt++) {
            int r0 = (mw * 32 + mt * 16 + gid) * 12 + tg;
            aH[mt][0] = __float_as_uint(WsH[r0]);
            aH[mt][1] = __float_as_uint(WsH[r0 + 96]);
            aH[mt][2] = __float_as_uint(WsH[r0 + 4]);
            aH[mt][3] = __float_as_uint(WsH[r0 + 100]);
            aL[mt][0] = __float_as_uint(WsL[r0]);
            aL[mt][1] = __float_as_uint(WsL[r0 + 96]);
            aL[mt][2] = __float_as_uint(WsL[r0 + 4]);
            aL[mt][3] = __float_as_uint(WsL[r0 + 100]);
        }
#pragma unroll
        for (int nt = 0; nt < 7; nt++) {
            int col = nw * 56 + nt * 8 + gid;
            uint32_t b0H = __float_as_uint(BsH[tg*120 + col]);
            uint32_t b1H = __float_as_uint(BsH[(tg+4)*120 + col]);
            uint32_t b0L = __float_as_uint(BsL[tg*120 + col]);
            uint32_t b1L = __float_as_uint(BsL[(tg+4)*120 + col]);
#pragma unroll
            for (int mt = 0; mt < 2; mt++) {
                mma_tf32(c[mt][nt], aH[mt], b0H, b1H);
                mma_tf32(c[mt][nt], aH[mt], b0L, b1L);
                mma_tf32(c[mt][nt], aL[mt], b0H, b1H);
            }
        }
    }

#pragma unroll
    for (int mt = 0; mt < 2; mt++) {
#pragma unroll
        for (int half = 0; half < 2; half++) {
            int o = mw * 32 + mt * 16 + gid + half * 8;
            float* outp = g_y1 + ((size_t)(n * C_ + o)) * P_ + pbase;
#pragma unroll
            for (int nt = 0; nt < 7; nt++) {
                int w0 = nw * 56 + nt * 8 + tg * 2;
                outp[w0]     = c[mt][nt][half * 2 + 0];
                outp[w0 + 1] = c[mt][nt][half * 2 + 1];
            }
        }
    }
}

// ---------------- BN statistics (deterministic, one block per channel) ----------------
__global__ void bnstats_kernel(int which) {
    const float* y = which ? g_y3 : g_y1;
    int c = blockIdx.x;
    int tid = threadIdx.x;
    float s = 0.f, s2 = 0.f;
    for (int n = 0; n < N_; n++) {
        const float* p = y + (n * C_ + c) * P_;
        for (int i = tid; i < P_; i += 256) {
            float v = p[i];
            s += v; s2 += v * v;
        }
    }
    __shared__ float rs[256], rq[256];
    rs[tid] = s; rq[tid] = s2;
    __syncthreads();
    for (int st = 128; st > 0; st >>= 1) {
        if (tid < st) { rs[tid] += rs[tid+st]; rq[tid] += rq[tid+st]; }
        __syncthreads();
    }
    if (tid == 0) {
        float cnt = (float)(N_ * P_);
        float m = rs[0] / cnt;
        float var = rq[0] / cnt - m * m;
        g_stats[which*128 + c]      = m;
        g_stats[which*128 + 64 + c] = rsqrtf(var + 1e-5f);
    }
}

// ---------------- BN1 apply + relu -> padded buffer for conv2 ----------------
__global__ void bnrelu_kernel(const float* __restrict__ gamma, const float* __restrict__ beta) {
    int idx = blockIdx.x * 256 + threadIdx.x;
    if (idx >= N_*C_*P_) return;
    int c = (idx / P_) % C_;
    float m = g_stats[c], is = g_stats[64 + c];
    float v = (g_y1[idx] - m) * is * gamma[c] + beta[c];
    v = fmaxf(v, 0.f);
    int pp = idx % P_;
    int w = pp % W_, hh = (pp / W_) % H_, dd = pp / (W_*H_);
    int nc = idx / P_;
    g_y2pad[nc * PPAD_ + (dd+1) * (HP_*WP_) + (hh+1) * WP_ + (w+1)] = v;
}

// ---------------- kernel 5: conv2 as 3xtf32 implicit GEMM -------
__global__ __launch_bounds__(256) void conv2_mma_kernel(const float* __restrict__ w2,
                                                        const float* __restrict__ b2) {
    __shared__ float WsH[64*36];
    __shared__ float WsL[64*36];
    __shared__ float slabH[1044];
    __shared__ float slabL[1044];
    __shared__ int   lut[32];

    int bx = blockIdx.x;
    int hq = bx % 14;
    int h  = hq * 4;
    int d  = (bx / 14) % D_;
    int n  = bx / (14 * D_);

    int tid  = threadIdx.x;
    int lane = tid & 31, warp = tid >> 5;
    int gid  = lane >> 2, tg = lane & 3;
    int mw   = warp >> 2, nw = warp & 3;

    if (tid < 32) {
        int j = tid, base = 0;
        if (j < 27) {
            int kd = j / 9, kh = (j / 3) % 3, kw = j % 3;
            base = kd * 348 + kh * 58 + kw;
        }
        lut[j] = base;
    }

    float c[2][7][4];
#pragma unroll
    for (int mt = 0; mt < 2; mt++)
#pragma unroll
        for (int nt = 0; nt < 7; nt++)
#pragma unroll
            for (int i = 0; i < 4; i++) c[mt][nt][i] = 0.f;

    const float* xp = g_y2pad + n * (C_*PPAD_) + d * HPWP_ + h * WP_;

    for (int ci = 0; ci < C_; ci++) {
        __syncthreads();
        const float* wsrc = w2 + (size_t)ci * 27;
#pragma unroll
        for (int i = tid; i < 2048; i += 256) {
            int co = i >> 5, j = i & 31;
            float v = 0.f;
            if (j < 27) v = wsrc[(size_t)co * 1728 + j];
            uint32_t hi = f2tf32(v);
            float lo = v - __uint_as_float(hi);
            WsH[co * 36 + j] = __uint_as_float(hi);
            WsL[co * 36 + j] = __uint_as_float(f2tf32(lo));
        }
        const float* src = xp + (size_t)ci * PPAD_;
#pragma unroll
        for (int i = tid; i < 1044; i += 256) {
            int kd = i / 348;
            int r2 = i - kd * 348;
            int hh = r2 / 58;
            int ww = r2 - hh * 58;
            float v = src[kd * HPWP_ + hh * WP_ + ww];
            uint32_t hi = f2tf32(v);
            float lo = v - __uint_as_float(hi);
            slabH[i] = __uint_as_float(hi);
            slabL[i] = __uint_as_float(f2tf32(lo));
        }
        __syncthreads();

#pragma unroll
        for (int ks = 0; ks < 4; ks++) {
            int l0 = lut[ks * 8 + tg];
            int l1 = lut[ks * 8 + tg + 4];
            uint32_t aH[2][4], aL[2][4];
#pragma unroll
            for (int mt = 0; mt < 2; mt++) {
                int rbase = (mw * 32 + mt * 16 + gid) * 36 + ks * 8 + tg;
                aH[mt][0] = __float_as_uint(WsH[rbase]);
                aH[mt][1] = __float_as_uint(WsH[rbase + 8*36]);
                aH[mt][2] = __float_as_uint(WsH[rbase + 4]);
                aH[mt][3] = __float_as_uint(WsH[rbase + 8*36 + 4]);
                aL[mt][0] = __float_as_uint(WsL[rbase]);
                aL[mt][1] = __float_as_uint(WsL[rbase + 8*36]);
                aL[mt][2] = __float_as_uint(WsL[rbase + 4]);
                aL[mt][3] = __float_as_uint(WsL[rbase + 8*36 + 4]);
            }
            int ro = nw * 58 + gid;
#pragma unroll
            for (int nt = 0; nt < 7; nt++) {
                uint32_t bH0 = __float_as_uint(slabH[l0 + ro]);
                uint32_t bH1 = __float_as_uint(slabH[l1 + ro]);
                uint32_t bL0 = __float_as_uint(slabL[l0 + ro]);
                uint32_t bL1 = __float_as_uint(slabL[l1 + ro]);
#pragma unroll
                for (int mt = 0; mt < 2; mt++) {
                    mma_tf32(c[mt][nt], aH[mt], bH0, bH1);
                    mma_tf32(c[mt][nt], aH[mt], bL0, bL1);
                    mma_tf32(c[mt][nt], aL[mt], bH0, bH1);
                }
                ro += 8;
            }
        }
    }

    int hrow = h + nw;
    int pbase = (d * H_ + hrow) * W_;
#pragma unroll
    for (int mt = 0; mt < 2; mt++) {
        int co0 = mw * 32 + mt * 16 + gid;
#pragma unroll
        for (int half = 0; half < 2; half++) {
            int co = co0 + half * 8;
            float bo = b2[co];
            float* outp = g_y3 + ((size_t)(n * C_ + co)) * P_ + pbase;
#pragma unroll
            for (int nt = 0; nt < 7; nt++) {
                int w0 = nt * 8 + tg * 2;
                outp[w0]     = c[mt][nt][half * 2 + 0] + bo;
                outp[w0 + 1] = c[mt][nt][half * 2 + 1] + bo;
            }
        }
    }
}

// ---------------- final: bn2 + residual + relu ----------------
__global__ void final_kernel(const float* __restrict__ x,
                             const float* __restrict__ gamma2,
                             const float* __restrict__ beta2,
                             float* __restrict__ out) {
    int idx = blockIdx.x * 256 + threadIdx.x;
    if (idx >= N_*C_*P_) return;
    int c = (idx / P_) % C_;
    float m = g_stats[128 + c], is = g_stats[192 + c];
    float v = (g_y3[idx] - m) * is * gamma2[c] + beta2[c] + x[idx];
    out[idx] = fmaxf(v, 0.f);
}

// ---------------- launcher ----------------
extern "C" void kernel_launch(void* const* d_in, const int* in_sizes, int n_in,
                              void* d_out, int out_size) {
    const float* x      = (const float*)d_in[0];
    const float* w_off  = (const float*)d_in[1];
    const float* b_off  = (const float*)d_in[2];
    const float* w1     = (const float*)d_in[3];
    const float* gamma1 = (const float*)d_in[4];
    const float* beta1  = (const float*)d_in[5];
    const float* w2     = (const float*)d_in[6];
    const float* b2     = (const float*)d_in[7];
    const float* gamma2 = (const float*)d_in[8];
    const float* beta2  = (const float*)d_in[9];
    float* out = (float*)d_out;

    int padtot = N_*C_*PPAD_;
    int tot = N_*C_*P_;

    padinit_kernel<<<(padtot + 255) / 256, 256>>>(x);
    offconv_mma_kernel<<<dim3(224, 11), 256>>>(w_off, b_off);
    deform_gather_kernel<<<N_*G_*K_*98, 256>>>(x);
    deform_gemm_kernel<<<448, 128>>>(w1);
    bnstats_kernel<<<64, 256>>>(0);
    bnrelu_kernel<<<(tot + 255) / 256, 256>>>(gamma1, beta1);
    conv2_mma_kernel<<<224, 256>>>(w2, b2);
    bnstats_kernel<<<64, 256>>>(1);
    final_kernel<<<(tot + 255) / 256, 256>>>(x, gamma2, beta2, out);
}

// round 6
// speedup vs baseline: 1.5527x; 1.1163x over previous
#include <cuda_runtime.h>
#include <cstdint>

#define N_ 2
#define C_ 64
#define D_ 8
#define H_ 56
#define W_ 56
#define G_ 8
#define K_ 27
#define CO_OFF 648
#define P_ (D_*H_*W_)          // 25088
#define DP_ (D_+2)
#define HP_ (H_+2)
#define WP_ (W_+2)
#define PPAD_ (DP_*HP_*WP_)    // 33640
#define HPWP_ (HP_*WP_)

#define PREP_W0 (11*64*64*32)  // 1441792
#define PREP_W1 (216*64*8)     // 110592
#define PREP_W2 (64*64*32)     // 131072
#define PREP_TOT (PREP_W0 + PREP_W1 + PREP_W2)

// ---------------- scratch (no allocation allowed) ----------------
__device__ float g_xpad[N_*C_*PPAD_];    // padded input for offset conv
__device__ float g_y2pad[N_*C_*PPAD_];   // padded bn1+relu output for conv2
__device__ float g_off[N_*CO_OFF*P_];    // offset tensor (130 MB)
__device__ float g_vals[N_*G_*K_*8*P_];  // sampled values (347 MB)
__device__ float g_y1[N_*C_*P_];         // deform conv output
__device__ float g_y3[N_*C_*P_];         // conv2 output
__device__ float g_stats[4*C_];          // mean1, istd1, mean2, istd2
__device__ float g_wofft[PREP_W0];       // tf32 w_off [cot][ci][co][j32]
__device__ float g_w1H[PREP_W1];         // w1 hi [t][o][cl]
__device__ float g_w1L[PREP_W1];         // w1 lo
__device__ float g_w2H[PREP_W2];         // w2 hi [ci][co][j32]
__device__ float g_w2L[PREP_W2];         // w2 lo

// ---------------- helpers ----------------
__device__ __forceinline__ uint32_t f2tf32(float x) {
    uint32_t r;
    asm("cvt.rna.tf32.f32 %0, %1;" : "=r"(r) : "f"(x));
    return r;
}

__device__ __forceinline__ void mma_tf32(float c[4], const uint32_t a[4],
                                         uint32_t b0, uint32_t b1) {
    asm volatile(
        "mma.sync.aligned.m16n8k8.row.col.f32.tf32.tf32.f32 "
        "{%0,%1,%2,%3}, {%4,%5,%6,%7}, {%8,%9}, {%0,%1,%2,%3};"
        : "+f"(c[0]), "+f"(c[1]), "+f"(c[2]), "+f"(c[3])
        : "r"(a[0]), "r"(a[1]), "r"(a[2]), "r"(a[3]), "r"(b0), "r"(b1));
}

// ---------------- kernel P: weight prep (tf32 / hi-lo, GEMM layouts) ----------------
__global__ void prep_kernel(const float* __restrict__ w_off,
                            const float* __restrict__ w1,
                            const float* __restrict__ w2) {
    int idx = blockIdx.x * 256 + threadIdx.x;
    if (idx < PREP_W0) {
        int j = idx & 31, co = (idx >> 5) & 63, ci = (idx >> 11) & 63, cot = idx >> 17;
        int cog = cot * 64 + co;
        float v = (j < 27 && cog < CO_OFF) ? w_off[(size_t)cog * 1728 + ci * 27 + j] : 0.f;
        g_wofft[idx] = __uint_as_float(f2tf32(v));
    } else if (idx < PREP_W0 + PREP_W1) {
        int r = idx - PREP_W0;
        int cl = r & 7, o = (r >> 3) & 63, t = r >> 9;
        int g = t / 27, k = t - g * 27;
        float v = w1[(o * C_ + g * 8 + cl) * K_ + k];
        uint32_t hi = f2tf32(v);
        float lo = v - __uint_as_float(hi);
        g_w1H[r] = __uint_as_float(hi);
        g_w1L[r] = __uint_as_float(f2tf32(lo));
    } else if (idx < PREP_TOT) {
        int r = idx - PREP_W0 - PREP_W1;
        int j = r & 31, co = (r >> 5) & 63, ci = r >> 11;
        float v = (j < 27) ? w2[(co * C_ + ci) * 27 + j] : 0.f;
        uint32_t hi = f2tf32(v);
        float lo = v - __uint_as_float(hi);
        g_w2H[r] = __uint_as_float(hi);
        g_w2L[r] = __uint_as_float(f2tf32(lo));
    }
}

// ---------------- kernel 0: build padded x, zero pad edges of y2pad ----------------
__global__ void padinit_kernel(const float* __restrict__ x) {
    int idx = blockIdx.x * 256 + threadIdx.x;
    if (idx >= N_*C_*PPAD_) return;
    int wp = idx % WP_;
    int hp = (idx / WP_) % HP_;
    int dp = (idx / (WP_*HP_)) % DP_;
    int nc = idx / PPAD_;
    bool interior = (dp >= 1 && dp <= D_ && hp >= 1 && hp <= H_ && wp >= 1 && wp <= W_);
    float v = 0.f;
    if (interior)
        v = x[nc * P_ + (dp-1) * (H_*W_) + (hp-1) * W_ + (wp-1)];
    g_xpad[idx] = v;
    if (!interior) g_y2pad[idx] = 0.f;
}

// ---------------- kernel 1: offset conv as tf32 implicit GEMM ----------
// BM=64 co x BN=224 positions. 256 thr, warps 2M x 4N. grid: (224, 11)
__global__ __launch_bounds__(256) void offconv_mma_kernel(const float* __restrict__ b_off) {
    __shared__ float Ws[64*36];     // weights [co][32k], stride 36
    __shared__ float slab[1044];    // xpad slab [kd 3][hh 6][ww 58] (tf32)
    __shared__ int   lut[32];       // tap -> slab base offset

    int bx = blockIdx.x;
    int hq = bx % 14;
    int h  = hq * 4;
    int d  = (bx / 14) % D_;
    int n  = bx / (14 * D_);
    int cot = blockIdx.y;

    int tid  = threadIdx.x;
    int lane = tid & 31, warp = tid >> 5;
    int gid  = lane >> 2, tg = lane & 3;
    int mw   = warp >> 2, nw = warp & 3;

    if (tid < 32) {
        int j = tid, base = 0;
        if (j < 27) {
            int kd = j / 9, kh = (j / 3) % 3, kw = j % 3;
            base = kd * 348 + kh * 58 + kw;
        }
        lut[j] = base;
    }

    float c[2][7][4];
#pragma unroll
    for (int mt = 0; mt < 2; mt++)
#pragma unroll
        for (int nt = 0; nt < 7; nt++)
#pragma unroll
            for (int i = 0; i < 4; i++) c[mt][nt][i] = 0.f;

    const float* xp = g_xpad + n * (C_*PPAD_) + d * HPWP_ + h * WP_;

    for (int ci = 0; ci < C_; ci++) {
        __syncthreads();
        // stage weights: 512 float4 (preconverted, GEMM layout)
        const float4* w4 = (const float4*)(g_wofft + (((size_t)cot * 64 + ci) << 11));
#pragma unroll
        for (int i = tid; i < 512; i += 256) {
            float4 v = w4[i];
            int co = i >> 3, j4 = (i & 7) * 4;
            *(float4*)&Ws[co * 36 + j4] = v;
        }
        // stage slab: 522 float2, tf32 cvt
        const float* src = xp + (size_t)ci * PPAD_;
#pragma unroll
        for (int i = tid; i < 522; i += 256) {
            int kd = i / 174;
            int r2 = i - kd * 174;
            int hh = r2 / 29;
            int w2i = r2 - hh * 29;
            float2 v = *(const float2*)&src[kd * HPWP_ + hh * WP_ + w2i * 2];
            float2 o;
            o.x = __uint_as_float(f2tf32(v.x));
            o.y = __uint_as_float(f2tf32(v.y));
            *(float2*)&slab[kd * 348 + hh * 58 + w2i * 2] = o;
        }
        __syncthreads();

#pragma unroll
        for (int ks = 0; ks < 4; ks++) {
            int l0 = lut[ks * 8 + tg];
            int l1 = lut[ks * 8 + tg + 4];
            uint32_t a[2][4];
#pragma unroll
            for (int mt = 0; mt < 2; mt++) {
                const float* wr = &Ws[(mw * 32 + mt * 16 + gid) * 36 + ks * 8 + tg];
                a[mt][0] = __float_as_uint(wr[0]);
                a[mt][1] = __float_as_uint(wr[8 * 36]);
                a[mt][2] = __float_as_uint(wr[4]);
                a[mt][3] = __float_as_uint(wr[8 * 36 + 4]);
            }
            int ro = nw * 58 + gid;
#pragma unroll
            for (int nt = 0; nt < 7; nt++) {
                uint32_t b0 = __float_as_uint(slab[l0 + ro]);
                uint32_t b1 = __float_as_uint(slab[l1 + ro]);
                mma_tf32(c[0][nt], a[0], b0, b1);
                mma_tf32(c[1][nt], a[1], b0, b1);
                ro += 8;
            }
        }
    }

    int hrow = h + nw;
    int pbase = (d * H_ + hrow) * W_;
#pragma unroll
    for (int mt = 0; mt < 2; mt++) {
        int co0 = cot * 64 + mw * 32 + mt * 16 + gid;
#pragma unroll
        for (int half = 0; half < 2; half++) {
            int co = co0 + half * 8;
            if (co < CO_OFF) {
                float bo = b_off[co];
                float* outp = g_off + ((size_t)(n * CO_OFF + co)) * P_ + pbase;
#pragma unroll
                for (int nt = 0; nt < 7; nt++) {
                    int w0 = nt * 8 + tg * 2;
                    float2 st;
                    st.x = c[mt][nt][half * 2 + 0] + bo;
                    st.y = c[mt][nt][half * 2 + 1] + bo;
                    *(float2*)&outp[w0] = st;
                }
            }
        }
    }
}

// ---------------- kernel 2a: deform gather (barrier-free) ----
// grid: N*G*K*98 blocks of 256
__global__ __launch_bounds__(256) void deform_gather_kernel(const float* __restrict__ x) {
    int bx = blockIdx.x;
    int pc = bx % 98;
    int ngk = bx / 98;
    int k = ngk % K_;
    int g = (ngk / K_) % G_;
    int n = ngk / (K_ * G_);
    int p = pc * 256 + threadIdx.x;

    int w = p % W_;
    int h = (p / W_) % H_;
    int d = p / (W_ * H_);

    int kd = k / 9, kh = (k / 3) % 3, kw = k % 3;
    size_t obase = ((size_t)(n * CO_OFF + (g*K_ + k) * 3)) * P_ + p;
    float od = __ldg(&g_off[obase]);
    float oh = __ldg(&g_off[obase + P_]);
    float ow = __ldg(&g_off[obase + 2*(size_t)P_]);

    float pd = (float)(d + kd - 1) + od;
    float ph = (float)(h + kh - 1) + oh;
    float pw = (float)(w + kw - 1) + ow;
    float d0f = floorf(pd), h0f = floorf(ph), w0f = floorf(pw);
    float fd = pd - d0f, fh = ph - h0f, fw = pw - w0f;
    int d0 = (int)d0f, h0 = (int)h0f, w0 = (int)w0f;

    int   clin[8];
    float cwgt[8];
#pragma unroll
    for (int c8 = 0; c8 < 8; c8++) {
        int cd = c8 >> 2, ch = (c8 >> 1) & 1, cw = c8 & 1;
        int id = d0 + cd, ih = h0 + ch, iw = w0 + cw;
        float wt = (cd ? fd : 1.f - fd) * (ch ? fh : 1.f - fh) * (cw ? fw : 1.f - fw);
        bool valid = (id >= 0 && id < D_ && ih >= 0 && ih < H_ && iw >= 0 && iw < W_);
        int idc = min(max(id, 0), D_-1);
        int ihc = min(max(ih, 0), H_-1);
        int iwc = min(max(iw, 0), W_-1);
        clin[c8] = (idc * H_ + ihc) * W_ + iwc;
        cwgt[c8] = valid ? wt : 0.f;
    }

    const float* xg = x + ((size_t)(n * C_ + g * 8)) * P_;
    float* vout = g_vals + ((size_t)(((n * G_ + g) * K_ + k) * 8)) * P_ + p;
#pragma unroll
    for (int cl = 0; cl < 8; cl++) {
        const float* xc = xg + (size_t)cl * P_;
        float s = 0.f;
#pragma unroll
        for (int c8 = 0; c8 < 8; c8++)
            s += __ldg(&xc[clin[c8]]) * cwgt[c8];
        vout[(size_t)cl * P_] = s;
    }
}

// ---------------- kernel 2b: deform GEMM (3xtf32, 2-tap double stage) -----
// BM=64 x BN=112 (rows h,h+1 of one (n,d)). 128 thr, warps 2M x 2N. grid: 448
__global__ __launch_bounds__(128) void deform_gemm_kernel() {
    __shared__ float WsH[2][64*12];
    __shared__ float WsL[2][64*12];
    __shared__ float BsH[2][8*120];
    __shared__ float BsL[2][8*120];

    int bx = blockIdx.x;
    int hq = bx % 28;
    int h  = hq * 2;
    int d  = (bx / 28) % D_;
    int n  = bx / (28 * D_);

    int tid  = threadIdx.x;
    int lane = tid & 31, warp = tid >> 5;
    int gid  = lane >> 2, tg = lane & 3;
    int mw   = warp >> 1, nw = warp & 1;

    float c[2][7][4];
#pragma unroll
    for (int mt = 0; mt < 2; mt++)
#pragma unroll
        for (int nt = 0; nt < 7; nt++)
#pragma unroll
            for (int i = 0; i < 4; i++) c[mt][nt][i] = 0.f;

    int pbase = (d * H_ + h) * W_;

    for (int t2 = 0; t2 < 108; t2++) {
        __syncthreads();
#pragma unroll
        for (int b = 0; b < 2; b++) {
            int t = t2 * 2 + b;
            // A: preconverted hi/lo, 128 float4 each (1 per thread)
            {
                float4 vh = ((const float4*)(g_w1H + ((size_t)t << 9)))[tid];
                float4 vl = ((const float4*)(g_w1L + ((size_t)t << 9)))[tid];
                int o = tid >> 1, c4 = (tid & 1) * 4;
                *(float4*)&WsH[b][o * 12 + c4] = vh;
                *(float4*)&WsL[b][o * 12 + c4] = vl;
            }
            // B: 224 float4 from vals, cvt hi/lo
            const float* vsrc = g_vals + ((size_t)t * 8) * P_ +
                                ((size_t)n * G_ * K_ * 8) * P_ + pbase;
#pragma unroll
            for (int i = tid; i < 224; i += 128) {
                int cl = i / 28, p4 = (i - cl * 28) * 4;
                float4 v = *(const float4*)&vsrc[(size_t)cl * P_ + p4];
                float4 hi, lo;
                hi.x = __uint_as_float(f2tf32(v.x)); lo.x = __uint_as_float(f2tf32(v.x - hi.x));
                hi.y = __uint_as_float(f2tf32(v.y)); lo.y = __uint_as_float(f2tf32(v.y - hi.y));
                hi.z = __uint_as_float(f2tf32(v.z)); lo.z = __uint_as_float(f2tf32(v.z - hi.z));
                hi.w = __uint_as_float(f2tf32(v.w)); lo.w = __uint_as_float(f2tf32(v.w - hi.w));
                *(float4*)&BsH[b][cl * 120 + p4] = hi;
                *(float4*)&BsL[b][cl * 120 + p4] = lo;
            }
        }
        __syncthreads();

#pragma unroll
        for (int b = 0; b < 2; b++) {
            uint32_t aH[2][4], aL[2][4];
#pragma unroll
            for (int mt = 0; mt < 2; mt++) {
                int r0 = (mw * 32 + mt * 16 + gid) * 12 + tg;
                aH[mt][0] = __float_as_uint(WsH[b][r0]);
                aH[mt][1] = __float_as_uint(WsH[b][r0 + 96]);
                aH[mt][2] = __float_as_uint(WsH[b][r0 + 4]);
                aH[mt][3] = __float_as_uint(WsH[b][r0 + 100]);
                aL[mt][0] = __float_as_uint(WsL[b][r0]);
                aL[mt][1] = __float_as_uint(WsL[b][r0 + 96]);
                aL[mt][2] = __float_as_uint(WsL[b][r0 + 4]);
                aL[mt][3] = __float_as_uint(WsL[b][r0 + 100]);
            }
#pragma unroll
            for (int nt = 0; nt < 7; nt++) {
                int col = nw * 56 + nt * 8 + gid;
                uint32_t b0H = __float_as_uint(BsH[b][tg*120 + col]);
                uint32_t b1H = __float_as_uint(BsH[b][(tg+4)*120 + col]);
                uint32_t b0L = __float_as_uint(BsL[b][tg*120 + col]);
                uint32_t b1L = __float_as_uint(BsL[b][(tg+4)*120 + col]);
#pragma unroll
                for (int mt = 0; mt < 2; mt++) {
                    mma_tf32(c[mt][nt], aH[mt], b0H, b1H);
                    mma_tf32(c[mt][nt], aH[mt], b0L, b1L);
                    mma_tf32(c[mt][nt], aL[mt], b0H, b1H);
                }
            }
        }
    }

#pragma unroll
    for (int mt = 0; mt < 2; mt++) {
#pragma unroll
        for (int half = 0; half < 2; half++) {
            int o = mw * 32 + mt * 16 + gid + half * 8;
            float* outp = g_y1 + ((size_t)(n * C_ + o)) * P_ + pbase;
#pragma unroll
            for (int nt = 0; nt < 7; nt++) {
                int w0 = nw * 56 + nt * 8 + tg * 2;
                float2 st;
                st.x = c[mt][nt][half * 2 + 0];
                st.y = c[mt][nt][half * 2 + 1];
                *(float2*)&outp[w0] = st;
            }
        }
    }
}

// ---------------- BN statistics (deterministic, one block per channel) ----------------
__global__ void bnstats_kernel(int which) {
    const float* y = which ? g_y3 : g_y1;
    int c = blockIdx.x;
    int tid = threadIdx.x;
    float s = 0.f, s2 = 0.f;
    for (int n = 0; n < N_; n++) {
        const float* p = y + (n * C_ + c) * P_;
        for (int i = tid; i < P_ / 4; i += 256) {
            float4 v = *(const float4*)&p[i * 4];
            s += v.x + v.y + v.z + v.w;
            s2 += v.x*v.x + v.y*v.y + v.z*v.z + v.w*v.w;
        }
    }
    __shared__ float rs[256], rq[256];
    rs[tid] = s; rq[tid] = s2;
    __syncthreads();
    for (int st = 128; st > 0; st >>= 1) {
        if (tid < st) { rs[tid] += rs[tid+st]; rq[tid] += rq[tid+st]; }
        __syncthreads();
    }
    if (tid == 0) {
        float cnt = (float)(N_ * P_);
        float m = rs[0] / cnt;
        float var = rq[0] / cnt - m * m;
        g_stats[which*128 + c]      = m;
        g_stats[which*128 + 64 + c] = rsqrtf(var + 1e-5f);
    }
}

// ---------------- BN1 apply + relu -> padded buffer for conv2 ----------------
__global__ void bnrelu_kernel(const float* __restrict__ gamma, const float* __restrict__ beta) {
    int i4 = blockIdx.x * 256 + threadIdx.x;
    if (i4 >= N_*C_*P_/4) return;
    int idx = i4 * 4;
    int c = (idx / P_) % C_;
    float m = g_stats[c], is = g_stats[64 + c];
    float ga = gamma[c], be = beta[c];
    float4 v = *(const float4*)&g_y1[idx];
    v.x = fmaxf((v.x - m) * is * ga + be, 0.f);
    v.y = fmaxf((v.y - m) * is * ga + be, 0.f);
    v.z = fmaxf((v.z - m) * is * ga + be, 0.f);
    v.w = fmaxf((v.w - m) * is * ga + be, 0.f);
    int pp = idx % P_;
    int w = pp % W_, hh = (pp / W_) % H_, dd = pp / (W_*H_);
    int nc = idx / P_;
    float* dst = &g_y2pad[nc * PPAD_ + (dd+1) * HPWP_ + (hh+1) * WP_ + (w+1)];
    dst[0] = v.x; dst[1] = v.y; dst[2] = v.z; dst[3] = v.w;
}

// ---------------- kernel 5: conv2 as 3xtf32 implicit GEMM -------
__global__ __launch_bounds__(256) void conv2_mma_kernel(const float* __restrict__ b2) {
    __shared__ float WsH[64*36];
    __shared__ float WsL[64*36];
    __shared__ float slabH[1044];
    __shared__ float slabL[1044];
    __shared__ int   lut[32];

    int bx = blockIdx.x;
    int hq = bx % 14;
    int h  = hq * 4;
    int d  = (bx / 14) % D_;
    int n  = bx / (14 * D_);

    int tid  = threadIdx.x;
    int lane = tid & 31, warp = tid >> 5;
    int gid  = lane >> 2, tg = lane & 3;
    int mw   = warp >> 2, nw = warp & 3;

    if (tid < 32) {
        int j = tid, base = 0;
        if (j < 27) {
            int kd = j / 9, kh = (j / 3) % 3, kw = j % 3;
            base = kd * 348 + kh * 58 + kw;
        }
        lut[j] = base;
    }

    float c[2][7][4];
#pragma unroll
    for (int mt = 0; mt < 2; mt++)
#pragma unroll
        for (int nt = 0; nt < 7; nt++)
#pragma unroll
            for (int i = 0; i < 4; i++) c[mt][nt][i] = 0.f;

    const float* xp = g_y2pad + n * (C_*PPAD_) + d * HPWP_ + h * WP_;

    for (int ci = 0; ci < C_; ci++) {
        __syncthreads();
        const float4* wh4 = (const float4*)(g_w2H + ((size_t)ci << 11));
        const float4* wl4 = (const float4*)(g_w2L + ((size_t)ci << 11));
#pragma unroll
        for (int i = tid; i < 512; i += 256) {
            float4 vh = wh4[i], vl = wl4[i];
            int co = i >> 3, j4 = (i & 7) * 4;
            *(float4*)&WsH[co * 36 + j4] = vh;
            *(float4*)&WsL[co * 36 + j4] = vl;
        }
        const float* src = xp + (size_t)ci * PPAD_;
#pragma unroll
        for (int i = tid; i < 522; i += 256) {
            int kd = i / 174;
            int r2 = i - kd * 174;
            int hh = r2 / 29;
            int w2i = r2 - hh * 29;
            float2 v = *(const float2*)&src[kd * HPWP_ + hh * WP_ + w2i * 2];
            float2 hi, lo;
            hi.x = __uint_as_float(f2tf32(v.x)); lo.x = __uint_as_float(f2tf32(v.x - hi.x));
            hi.y = __uint_as_float(f2tf32(v.y)); lo.y = __uint_as_float(f2tf32(v.y - hi.y));
            int so = kd * 348 + hh * 58 + w2i * 2;
            *(float2*)&slabH[so] = hi;
            *(float2*)&slabL[so] = lo;
        }
        __syncthreads();

#pragma unroll
        for (int ks = 0; ks < 4; ks++) {
            int l0 = lut[ks * 8 + tg];
            int l1 = lut[ks * 8 + tg + 4];
            uint32_t aH[2][4], aL[2][4];
#pragma unroll
            for (int mt = 0; mt < 2; mt++) {
                int rbase = (mw * 32 + mt * 16 + gid) * 36 + ks * 8 + tg;
                aH[mt][0] = __float_as_uint(WsH[rbase]);
                aH[mt][1] = __float_as_uint(WsH[rbase + 8*36]);
                aH[mt][2] = __float_as_uint(WsH[rbase + 4]);
                aH[mt][3] = __float_as_uint(WsH[rbase + 8*36 + 4]);
                aL[mt][0] = __float_as_uint(WsL[rbase]);
                aL[mt][1] = __float_as_uint(WsL[rbase + 8*36]);
                aL[mt][2] = __float_as_uint(WsL[rbase + 4]);
                aL[mt][3] = __float_as_uint(WsL[rbase + 8*36 + 4]);
            }
            int ro = nw * 58 + gid;
#pragma unroll
            for (int nt = 0; nt < 7; nt++) {
                uint32_t bH0 = __float_as_uint(slabH[l0 + ro]);
                uint32_t bH1 = __float_as_uint(slabH[l1 + ro]);
                uint32_t bL0 = __float_as_uint(slabL[l0 + ro]);
                uint32_t bL1 = __float_as_uint(slabL[l1 + ro]);
#pragma unroll
                for (int mt = 0; mt < 2; mt++) {
                    mma_tf32(c[mt][nt], aH[mt], bH0, bH1);
                    mma_tf32(c[mt][nt], aH[mt], bL0, bL1);
                    mma_tf32(c[mt][nt], aL[mt], bH0, bH1);
                }
                ro += 8;
            }
        }
    }

    int hrow = h + nw;
    int pbase = (d * H_ + hrow) * W_;
#pragma unroll
    for (int mt = 0; mt < 2; mt++) {
        int co0 = mw * 32 + mt * 16 + gid;
#pragma unroll
        for (int half = 0; half < 2; half++) {
            int co = co0 + half * 8;
            float bo = b2[co];
            float* outp = g_y3 + ((size_t)(n * C_ + co)) * P_ + pbase;
#pragma unroll
            for (int nt = 0; nt < 7; nt++) {
                int w0 = nt * 8 + tg * 2;
                float2 st;
                st.x = c[mt][nt][half * 2 + 0] + bo;
                st.y = c[mt][nt][half * 2 + 1] + bo;
                *(float2*)&outp[w0] = st;
            }
        }
    }
}

// ---------------- final: bn2 + residual + relu (float4) ----------------
__global__ void final_kernel(const float* __restrict__ x,
                             const float* __restrict__ gamma2,
                             const float* __restrict__ beta2,
                             float* __restrict__ out) {
    int i4 = blockIdx.x * 256 + threadIdx.x;
    if (i4 >= N_*C_*P_/4) return;
    int idx = i4 * 4;
    int c = (idx / P_) % C_;
    float m = g_stats[128 + c], is = g_stats[192 + c];
    float ga = gamma2[c], be = beta2[c];
    float4 v = *(const float4*)&g_y3[idx];
    float4 xr = *(const float4*)&x[idx];
    float4 o;
    o.x = fmaxf((v.x - m) * is * ga + be + xr.x, 0.f);
    o.y = fmaxf((v.y - m) * is * ga + be + xr.y, 0.f);
    o.z = fmaxf((v.z - m) * is * ga + be + xr.z, 0.f);
    o.w = fmaxf((v.w - m) * is * ga + be + xr.w, 0.f);
    *(float4*)&out[idx] = o;
}

// ---------------- launcher ----------------
extern "C" void kernel_launch(void* const* d_in, const int* in_sizes, int n_in,
                              void* d_out, int out_size) {
    const float* x      = (const float*)d_in[0];
    const float* w_off  = (const float*)d_in[1];
    const float* b_off  = (const float*)d_in[2];
    const float* w1     = (const float*)d_in[3];
    const float* gamma1 = (const float*)d_in[4];
    const float* beta1  = (const float*)d_in[5];
    const float* w2     = (const float*)d_in[6];
    const float* b2     = (const float*)d_in[7];
    const float* gamma2 = (const float*)d_in[8];
    const float* beta2  = (const float*)d_in[9];
    float* out = (float*)d_out;

    int padtot = N_*C_*PPAD_;
    int tot4 = N_*C_*P_/4;

    prep_kernel<<<(PREP_TOT + 255) / 256, 256>>>(w_off, w1, w2);
    padinit_kernel<<<(padtot + 255) / 256, 256>>>(x);
    offconv_mma_kernel<<<dim3(224, 11), 256>>>(b_off);
    deform_gather_kernel<<<N_*G_*K_*98, 256>>>(x);
    deform_gemm_kernel<<<448, 128>>>();
    bnstats_kernel<<<64, 256>>>(0);
    bnrelu_kernel<<<(tot4 + 255) / 256, 256>>>(gamma1, beta1);
    conv2_mma_kernel<<<224, 256>>>(b2);
    bnstats_kernel<<<64, 256>>>(1);
    final_kernel<<<(tot4 + 255) / 256, 256>>>(x, gamma2, beta2, out);
}

// round 7
// speedup vs baseline: 1.5823x; 1.0190x over previous
#include <cuda_runtime.h>
#include <cstdint>

#define N_ 2
#define C_ 64
#define D_ 8
#define H_ 56
#define W_ 56
#define G_ 8
#define K_ 27
#define CO_OFF 648
#define P_ (D_*H_*W_)          // 25088
#define DP_ (D_+2)
#define HP_ (H_+2)
#define WP_ (W_+2)
#define PPAD_ (DP_*HP_*WP_)    // 33640
#define HPWP_ (HP_*WP_)

#define PREP_W0 (11*64*64*32)  // 1441792
#define PREP_W1 (216*64*8)     // 110592
#define PREP_W2 (64*64*32)     // 131072
#define PREP_TOT (PREP_W0 + PREP_W1 + PREP_W2)

// ---------------- scratch (no allocation allowed) ----------------
__device__ float g_xpad[N_*C_*PPAD_];    // padded input for offset conv
__device__ float g_y2pad[N_*C_*PPAD_];   // padded bn1+relu output for conv2
__device__ float g_off[N_*CO_OFF*P_];    // offset tensor (130 MB)
__device__ float4 g_xt[N_*G_*P_*2];      // x transposed [n][g][p][8ch] (12.8 MB)
__device__ float g_vals[N_*G_*K_*8*P_];  // sampled values (347 MB)
__device__ float g_y1[N_*C_*P_];         // deform conv output
__device__ float g_y3[N_*C_*P_];         // conv2 output
__device__ float g_stats[4*C_];          // mean1, istd1, mean2, istd2
__device__ float g_wofft[PREP_W0];       // tf32 w_off [cot][ci][co][j32]
__device__ float g_w1H[PREP_W1];         // w1 tf32 [t][o][cl]
__device__ float g_w2H[PREP_W2];         // w2 tf32 [ci][co][j32]

// ---------------- helpers ----------------
__device__ __forceinline__ uint32_t f2tf32(float x) {
    uint32_t r;
    asm("cvt.rna.tf32.f32 %0, %1;" : "=r"(r) : "f"(x));
    return r;
}

__device__ __forceinline__ void mma_tf32(float c[4], const uint32_t a[4],
                                         uint32_t b0, uint32_t b1) {
    asm volatile(
        "mma.sync.aligned.m16n8k8.row.col.f32.tf32.tf32.f32 "
        "{%0,%1,%2,%3}, {%4,%5,%6,%7}, {%8,%9}, {%0,%1,%2,%3};"
        : "+f"(c[0]), "+f"(c[1]), "+f"(c[2]), "+f"(c[3])
        : "r"(a[0]), "r"(a[1]), "r"(a[2]), "r"(a[3]), "r"(b0), "r"(b1));
}

// ---------------- kernel P: weight prep (tf32, GEMM layouts) ----------------
__global__ void prep_kernel(const float* __restrict__ w_off,
                            const float* __restrict__ w1,
                            const float* __restrict__ w2) {
    int idx = blockIdx.x * 256 + threadIdx.x;
    if (idx < PREP_W0) {
        int j = idx & 31, co = (idx >> 5) & 63, ci = (idx >> 11) & 63, cot = idx >> 17;
        int cog = cot * 64 + co;
        float v = (j < 27 && cog < CO_OFF) ? w_off[(size_t)cog * 1728 + ci * 27 + j] : 0.f;
        g_wofft[idx] = __uint_as_float(f2tf32(v));
    } else if (idx < PREP_W0 + PREP_W1) {
        int r = idx - PREP_W0;
        int cl = r & 7, o = (r >> 3) & 63, t = r >> 9;
        int g = t / 27, k = t - g * 27;
        float v = w1[(o * C_ + g * 8 + cl) * K_ + k];
        g_w1H[r] = __uint_as_float(f2tf32(v));
    } else if (idx < PREP_TOT) {
        int r = idx - PREP_W0 - PREP_W1;
        int j = r & 31, co = (r >> 5) & 63, ci = r >> 11;
        float v = (j < 27) ? w2[(co * C_ + ci) * 27 + j] : 0.f;
        g_w2H[r] = __uint_as_float(f2tf32(v));
    }
}

// ---------------- kernel T: transpose x -> [n][g][p][8ch] ----------------
__global__ void transpose_kernel(const float* __restrict__ x) {
    int idx = blockIdx.x * 256 + threadIdx.x;   // n*g*p
    if (idx >= N_*G_*P_) return;
    int p = idx % P_;
    int g = (idx / P_) % G_;
    int n = idx / (P_ * G_);
    const float* xs = x + ((size_t)(n * C_ + g * 8)) * P_ + p;
    float4 a, b;
    a.x = xs[0];            a.y = xs[(size_t)P_];
    a.z = xs[2*(size_t)P_]; a.w = xs[3*(size_t)P_];
    b.x = xs[4*(size_t)P_]; b.y = xs[5*(size_t)P_];
    b.z = xs[6*(size_t)P_]; b.w = xs[7*(size_t)P_];
    g_xt[(size_t)idx * 2]     = a;
    g_xt[(size_t)idx * 2 + 1] = b;
}

// ---------------- kernel 0: build padded x, zero pad edges of y2pad ----------------
__global__ void padinit_kernel(const float* __restrict__ x) {
    int idx = blockIdx.x * 256 + threadIdx.x;
    if (idx >= N_*C_*PPAD_) return;
    int wp = idx % WP_;
    int hp = (idx / WP_) % HP_;
    int dp = (idx / (WP_*HP_)) % DP_;
    int nc = idx / PPAD_;
    bool interior = (dp >= 1 && dp <= D_ && hp >= 1 && hp <= H_ && wp >= 1 && wp <= W_);
    float v = 0.f;
    if (interior)
        v = x[nc * P_ + (dp-1) * (H_*W_) + (hp-1) * W_ + (wp-1)];
    g_xpad[idx] = v;
    if (!interior) g_y2pad[idx] = 0.f;
}

// ---------------- kernel 1: offset conv as tf32 implicit GEMM ----------
// BM=64 co x BN=224 positions. 256 thr, warps 2M x 4N. grid: (224, 11)
__global__ __launch_bounds__(256) void offconv_mma_kernel(const float* __restrict__ b_off) {
    __shared__ float Ws[64*36];     // weights [co][32k], stride 36
    __shared__ float slab[1044];    // xpad slab [kd 3][hh 6][ww 58] (tf32)
    __shared__ int   lut[32];       // tap -> slab base offset

    int bx = blockIdx.x;
    int hq = bx % 14;
    int h  = hq * 4;
    int d  = (bx / 14) % D_;
    int n  = bx / (14 * D_);
    int cot = blockIdx.y;

    int tid  = threadIdx.x;
    int lane = tid & 31, warp = tid >> 5;
    int gid  = lane >> 2, tg = lane & 3;
    int mw   = warp >> 2, nw = warp & 3;

    if (tid < 32) {
        int j = tid, base = 0;
        if (j < 27) {
            int kd = j / 9, kh = (j / 3) % 3, kw = j % 3;
            base = kd * 348 + kh * 58 + kw;
        }
        lut[j] = base;
    }

    float c[2][7][4];
#pragma unroll
    for (int mt = 0; mt < 2; mt++)
#pragma unroll
        for (int nt = 0; nt < 7; nt++)
#pragma unroll
            for (int i = 0; i < 4; i++) c[mt][nt][i] = 0.f;

    const float* xp = g_xpad + n * (C_*PPAD_) + d * HPWP_ + h * WP_;

    for (int ci = 0; ci < C_; ci++) {
        __syncthreads();
        const float4* w4 = (const float4*)(g_wofft + (((size_t)cot * 64 + ci) << 11));
#pragma unroll
        for (int i = tid; i < 512; i += 256) {
            float4 v = w4[i];
            int co = i >> 3, j4 = (i & 7) * 4;
            *(float4*)&Ws[co * 36 + j4] = v;
        }
        const float* src = xp + (size_t)ci * PPAD_;
#pragma unroll
        for (int i = tid; i < 522; i += 256) {
            int kd = i / 174;
            int r2 = i - kd * 174;
            int hh = r2 / 29;
            int w2i = r2 - hh * 29;
            float2 v = *(const float2*)&src[kd * HPWP_ + hh * WP_ + w2i * 2];
            float2 o;
            o.x = __uint_as_float(f2tf32(v.x));
            o.y = __uint_as_float(f2tf32(v.y));
            *(float2*)&slab[kd * 348 + hh * 58 + w2i * 2] = o;
        }
        __syncthreads();

#pragma unroll
        for (int ks = 0; ks < 4; ks++) {
            int l0 = lut[ks * 8 + tg];
            int l1 = lut[ks * 8 + tg + 4];
            uint32_t a[2][4];
#pragma unroll
            for (int mt = 0; mt < 2; mt++) {
                const float* wr = &Ws[(mw * 32 + mt * 16 + gid) * 36 + ks * 8 + tg];
                a[mt][0] = __float_as_uint(wr[0]);
                a[mt][1] = __float_as_uint(wr[8 * 36]);
                a[mt][2] = __float_as_uint(wr[4]);
                a[mt][3] = __float_as_uint(wr[8 * 36 + 4]);
            }
            int ro = nw * 58 + gid;
#pragma unroll
            for (int nt = 0; nt < 7; nt++) {
                uint32_t b0 = __float_as_uint(slab[l0 + ro]);
                uint32_t b1 = __float_as_uint(slab[l1 + ro]);
                mma_tf32(c[0][nt], a[0], b0, b1);
                mma_tf32(c[1][nt], a[1], b0, b1);
                ro += 8;
            }
        }
    }

    int hrow = h + nw;
    int pbase = (d * H_ + hrow) * W_;
#pragma unroll
    for (int mt = 0; mt < 2; mt++) {
        int co0 = cot * 64 + mw * 32 + mt * 16 + gid;
#pragma unroll
        for (int half = 0; half < 2; half++) {
            int co = co0 + half * 8;
            if (co < CO_OFF) {
                float bo = b_off[co];
                float* outp = g_off + ((size_t)(n * CO_OFF + co)) * P_ + pbase;
#pragma unroll
                for (int nt = 0; nt < 7; nt++) {
                    int w0 = nt * 8 + tg * 2;
                    float2 st;
                    st.x = c[mt][nt][half * 2 + 0] + bo;
                    st.y = c[mt][nt][half * 2 + 1] + bo;
                    *(float2*)&outp[w0] = st;
                }
            }
        }
    }
}

// ---------------- kernel 2a: deform gather (float4 channel-vectorized) ----
// grid: N*G*K*98 blocks of 256
__global__ __launch_bounds__(256) void deform_gather_kernel() {
    int bx = blockIdx.x;
    int pc = bx % 98;
    int ngk = bx / 98;
    int k = ngk % K_;
    int g = (ngk / K_) % G_;
    int n = ngk / (K_ * G_);
    int p = pc * 256 + threadIdx.x;

    int w = p % W_;
    int h = (p / W_) % H_;
    int d = p / (W_ * H_);

    int kd = k / 9, kh = (k / 3) % 3, kw = k % 3;
    size_t obase = ((size_t)(n * CO_OFF + (g*K_ + k) * 3)) * P_ + p;
    float od = __ldg(&g_off[obase]);
    float oh = __ldg(&g_off[obase + P_]);
    float ow = __ldg(&g_off[obase + 2*(size_t)P_]);

    float pd = (float)(d + kd - 1) + od;
    float ph = (float)(h + kh - 1) + oh;
    float pw = (float)(w + kw - 1) + ow;
    float d0f = floorf(pd), h0f = floorf(ph), w0f = floorf(pw);
    float fd = pd - d0f, fh = ph - h0f, fw = pw - w0f;
    int d0 = (int)d0f, h0 = (int)h0f, w0 = (int)w0f;

    const float4* xg = (const float4*)g_xt + ((size_t)(n * G_ + g)) * P_ * 2;

    float s0=0.f,s1=0.f,s2=0.f,s3=0.f,s4=0.f,s5=0.f,s6=0.f,s7=0.f;
#pragma unroll
    for (int c8 = 0; c8 < 8; c8++) {
        int cd = c8 >> 2, ch = (c8 >> 1) & 1, cw = c8 & 1;
        int id = d0 + cd, ih = h0 + ch, iw = w0 + cw;
        float wt = (cd ? fd : 1.f - fd) * (ch ? fh : 1.f - fh) * (cw ? fw : 1.f - fw);
        bool valid = (id >= 0 && id < D_ && ih >= 0 && ih < H_ && iw >= 0 && iw < W_);
        int idc = min(max(id, 0), D_-1);
        int ihc = min(max(ih, 0), H_-1);
        int iwc = min(max(iw, 0), W_-1);
        int lin = (idc * H_ + ihc) * W_ + iwc;
        wt = valid ? wt : 0.f;
        float4 va = __ldg(&xg[(size_t)lin * 2]);
        float4 vb = __ldg(&xg[(size_t)lin * 2 + 1]);
        s0 += va.x * wt; s1 += va.y * wt; s2 += va.z * wt; s3 += va.w * wt;
        s4 += vb.x * wt; s5 += vb.y * wt; s6 += vb.z * wt; s7 += vb.w * wt;
    }

    float* vout = g_vals + ((size_t)(((n * G_ + g) * K_ + k) * 8)) * P_ + p;
    vout[0]            = s0;
    vout[(size_t)P_]   = s1;
    vout[2*(size_t)P_] = s2;
    vout[3*(size_t)P_] = s3;
    vout[4*(size_t)P_] = s4;
    vout[5*(size_t)P_] = s5;
    vout[6*(size_t)P_] = s6;
    vout[7*(size_t)P_] = s7;
}

// ---------------- kernel 2b: deform GEMM (2-term tf32, 2-tap double stage) -----
// BM=64 x BN=112 (rows h,h+1 of one (n,d)). 128 thr, warps 2M x 2N. grid: 448
__global__ __launch_bounds__(128) void deform_gemm_kernel() {
    __shared__ float WsH[2][64*12];
    __shared__ float BsH[2][8*120];
    __shared__ float BsL[2][8*120];

    int bx = blockIdx.x;
    int hq = bx % 28;
    int h  = hq * 2;
    int d  = (bx / 28) % D_;
    int n  = bx / (28 * D_);

    int tid  = threadIdx.x;
    int lane = tid & 31, warp = tid >> 5;
    int gid  = lane >> 2, tg = lane & 3;
    int mw   = warp >> 1, nw = warp & 1;

    float c[2][7][4];
#pragma unroll
    for (int mt = 0; mt < 2; mt++)
#pragma unroll
        for (int nt = 0; nt < 7; nt++)
#pragma unroll
            for (int i = 0; i < 4; i++) c[mt][nt][i] = 0.f;

    int pbase = (d * H_ + h) * W_;

    for (int t2 = 0; t2 < 108; t2++) {
        __syncthreads();
#pragma unroll
        for (int b = 0; b < 2; b++) {
            int t = t2 * 2 + b;
            // A: preconverted tf32, 128 float4 (1 per thread)
            {
                float4 vh = ((const float4*)(g_w1H + ((size_t)t << 9)))[tid];
                int o = tid >> 1, c4 = (tid & 1) * 4;
                *(float4*)&WsH[b][o * 12 + c4] = vh;
            }
            // B: 224 float4 from vals, cvt hi/lo
            const float* vsrc = g_vals + ((size_t)t * 8) * P_ +
                                ((size_t)n * G_ * K_ * 8) * P_ + pbase;
#pragma unroll
            for (int i = tid; i < 224; i += 128) {
                int cl = i / 28, p4 = (i - cl * 28) * 4;
                float4 v = *(const float4*)&vsrc[(size_t)cl * P_ + p4];
                float4 hi, lo;
                hi.x = __uint_as_float(f2tf32(v.x)); lo.x = __uint_as_float(f2tf32(v.x - hi.x));
                hi.y = __uint_as_float(f2tf32(v.y)); lo.y = __uint_as_float(f2tf32(v.y - hi.y));
                hi.z = __uint_as_float(f2tf32(v.z)); lo.z = __uint_as_float(f2tf32(v.z - hi.z));
                hi.w = __uint_as_float(f2tf32(v.w)); lo.w = __uint_as_float(f2tf32(v.w - hi.w));
                *(float4*)&BsH[b][cl * 120 + p4] = hi;
                *(float4*)&BsL[b][cl * 120 + p4] = lo;
            }
        }
        __syncthreads();

#pragma unroll
        for (int b = 0; b < 2; b++) {
            uint32_t aH[2][4];
#pragma unroll
            for (int mt = 0; mt < 2; mt++) {
                int r0 = (mw * 32 + mt * 16 + gid) * 12 + tg;
                aH[mt][0] = __float_as_uint(WsH[b][r0]);
                aH[mt][1] = __float_as_uint(WsH[b][r0 + 96]);
                aH[mt][2] = __float_as_uint(WsH[b][r0 + 4]);
                aH[mt][3] = __float_as_uint(WsH[b][r0 + 100]);
            }
#pragma unroll
            for (int nt = 0; nt < 7; nt++) {
                int col = nw * 56 + nt * 8 + gid;
                uint32_t b0H = __float_as_uint(BsH[b][tg*120 + col]);
                uint32_t b1H = __float_as_uint(BsH[b][(tg+4)*120 + col]);
                uint32_t b0L = __float_as_uint(BsL[b][tg*120 + col]);
                uint32_t b1L = __float_as_uint(BsL[b][(tg+4)*120 + col]);
#pragma unroll
                for (int mt = 0; mt < 2; mt++) {
                    mma_tf32(c[mt][nt], aH[mt], b0H, b1H);
                    mma_tf32(c[mt][nt], aH[mt], b0L, b1L);
                }
            }
        }
    }

#pragma unroll
    for (int mt = 0; mt < 2; mt++) {
#pragma unroll
        for (int half = 0; half < 2; half++) {
            int o = mw * 32 + mt * 16 + gid + half * 8;
            float* outp = g_y1 + ((size_t)(n * C_ + o)) * P_ + pbase;
#pragma unroll
            for (int nt = 0; nt < 7; nt++) {
                int w0 = nw * 56 + nt * 8 + tg * 2;
                float2 st;
                st.x = c[mt][nt][half * 2 + 0];
                st.y = c[mt][nt][half * 2 + 1];
                *(float2*)&outp[w0] = st;
            }
        }
    }
}

// ---------------- BN statistics (deterministic, one block per channel) ----------------
__global__ void bnstats_kernel(int which) {
    const float* y = which ? g_y3 : g_y1;
    int c = blockIdx.x;
    int tid = threadIdx.x;
    float s = 0.f, s2 = 0.f;
    for (int n = 0; n < N_; n++) {
        const float* p = y + (n * C_ + c) * P_;
        for (int i = tid; i < P_ / 4; i += 256) {
            float4 v = *(const float4*)&p[i * 4];
            s += v.x + v.y + v.z + v.w;
            s2 += v.x*v.x + v.y*v.y + v.z*v.z + v.w*v.w;
        }
    }
    __shared__ float rs[256], rq[256];
    rs[tid] = s; rq[tid] = s2;
    __syncthreads();
    for (int st = 128; st > 0; st >>= 1) {
        if (tid < st) { rs[tid] += rs[tid+st]; rq[tid] += rq[tid+st]; }
        __syncthreads();
    }
    if (tid == 0) {
        float cnt = (float)(N_ * P_);
        float m = rs[0] / cnt;
        float var = rq[0] / cnt - m * m;
        g_stats[which*128 + c]      = m;
        g_stats[which*128 + 64 + c] = rsqrtf(var + 1e-5f);
    }
}

// ---------------- BN1 apply + relu -> padded buffer for conv2 ----------------
__global__ void bnrelu_kernel(const float* __restrict__ gamma, const float* __restrict__ beta) {
    int i4 = blockIdx.x * 256 + threadIdx.x;
    if (i4 >= N_*C_*P_/4) return;
    int idx = i4 * 4;
    int c = (idx / P_) % C_;
    float m = g_stats[c], is = g_stats[64 + c];
    float ga = gamma[c], be = beta[c];
    float4 v = *(const float4*)&g_y1[idx];
    v.x = fmaxf((v.x - m) * is * ga + be, 0.f);
    v.y = fmaxf((v.y - m) * is * ga + be, 0.f);
    v.z = fmaxf((v.z - m) * is * ga + be, 0.f);
    v.w = fmaxf((v.w - m) * is * ga + be, 0.f);
    int pp = idx % P_;
    int w = pp % W_, hh = (pp / W_) % H_, dd = pp / (W_*H_);
    int nc = idx / P_;
    float* dst = &g_y2pad[nc * PPAD_ + (dd+1) * HPWP_ + (hh+1) * WP_ + (w+1)];
    dst[0] = v.x; dst[1] = v.y; dst[2] = v.z; dst[3] = v.w;
}

// ---------------- kernel 5: conv2 as 2-term tf32 implicit GEMM -------
__global__ __launch_bounds__(256) void conv2_mma_kernel(const float* __restrict__ b2) {
    __shared__ float Ws[64*36];
    __shared__ float slabH[1044];
    __shared__ float slabL[1044];
    __shared__ int   lut[32];

    int bx = blockIdx.x;
    int hq = bx % 14;
    int h  = hq * 4;
    int d  = (bx / 14) % D_;
    int n  = bx / (14 * D_);

    int tid  = threadIdx.x;
    int lane = tid & 31, warp = tid >> 5;
    int gid  = lane >> 2, tg = lane & 3;
    int mw   = warp >> 2, nw = warp & 3;

    if (tid < 32) {
        int j = tid, base = 0;
        if (j < 27) {
            int kd = j / 9, kh = (j / 3) % 3, kw = j % 3;
            base = kd * 348 + kh * 58 + kw;
        }
        lut[j] = base;
    }

    float c[2][7][4];
#pragma unroll
    for (int mt = 0; mt < 2; mt++)
#pragma unroll
        for (int nt = 0; nt < 7; nt++)
#pragma unroll
            for (int i = 0; i < 4; i++) c[mt][nt][i] = 0.f;

    const float* xp = g_y2pad + n * (C_*PPAD_) + d * HPWP_ + h * WP_;

    for (int ci = 0; ci < C_; ci++) {
        __syncthreads();
        const float4* wh4 = (const float4*)(g_w2H + ((size_t)ci << 11));
#pragma unroll
        for (int i = tid; i < 512; i += 256) {
            float4 vh = wh4[i];
            int co = i >> 3, j4 = (i & 7) * 4;
            *(float4*)&Ws[co * 36 + j4] = vh;
        }
        const float* src = xp + (size_t)ci * PPAD_;
#pragma unroll
        for (int i = tid; i < 522; i += 256) {
            int kd = i / 174;
            int r2 = i - kd * 174;
            int hh = r2 / 29;
            int w2i = r2 - hh * 29;
            float2 v = *(const float2*)&src[kd * HPWP_ + hh * WP_ + w2i * 2];
            float2 hi, lo;
            hi.x = __uint_as_float(f2tf32(v.x)); lo.x = __uint_as_float(f2tf32(v.x - hi.x));
            hi.y = __uint_as_float(f2tf32(v.y)); lo.y = __uint_as_float(f2tf32(v.y - hi.y));
            int so = kd * 348 + hh * 58 + w2i * 2;
            *(float2*)&slabH[so] = hi;
            *(float2*)&slabL[so] = lo;
        }
        __syncthreads();

#pragma unroll
        for (int ks = 0; ks < 4; ks++) {
            int l0 = lut[ks * 8 + tg];
            int l1 = lut[ks * 8 + tg + 4];
            uint32_t aH[2][4];
#pragma unroll
            for (int mt = 0; mt < 2; mt++) {
                int rbase = (mw * 32 + mt * 16 + gid) * 36 + ks * 8 + tg;
                aH[mt][0] = __float_as_uint(Ws[rbase]);
                aH[mt][1] = __float_as_uint(Ws[rbase + 8*36]);
                aH[mt][2] = __float_as_uint(Ws[rbase + 4]);
                aH[mt][3] = __float_as_uint(Ws[rbase + 8*36 + 4]);
            }
            int ro = nw * 58 + gid;
#pragma unroll
            for (int nt = 0; nt < 7; nt++) {
                uint32_t bH0 = __float_as_uint(slabH[l0 + ro]);
                uint32_t bH1 = __float_as_uint(slabH[l1 + ro]);
                uint32_t bL0 = __float_as_uint(slabL[l0 + ro]);
                uint32_t bL1 = __float_as_uint(slabL[l1 + ro]);
#pragma unroll
                for (int mt = 0; mt < 2; mt++) {
                    mma_tf32(c[mt][nt], aH[mt], bH0, bH1);
                    mma_tf32(c[mt][nt], aH[mt], bL0, bL1);
                }
                ro += 8;
            }
        }
    }

    int hrow = h + nw;
    int pbase = (d * H_ + hrow) * W_;
#pragma unroll
    for (int mt = 0; mt < 2; mt++) {
        int co0 = mw * 32 + mt * 16 + gid;
#pragma unroll
        for (int half = 0; half < 2; half++) {
            int co = co0 + half * 8;
            float bo = b2[co];
            float* outp = g_y3 + ((size_t)(n * C_ + co)) * P_ + pbase;
#pragma unroll
            for (int nt = 0; nt < 7; nt++) {
                int w0 = nt * 8 + tg * 2;
                float2 st;
                st.x = c[mt][nt][half * 2 + 0] + bo;
                st.y = c[mt][nt][half * 2 + 1] + bo;
                *(float2*)&outp[w0] = st;
            }
        }
    }
}

// ---------------- final: bn2 + residual + relu (float4) ----------------
__global__ void final_kernel(const float* __restrict__ x,
                             const float* __restrict__ gamma2,
                             const float* __restrict__ beta2,
                             float* __restrict__ out) {
    int i4 = blockIdx.x * 256 + threadIdx.x;
    if (i4 >= N_*C_*P_/4) return;
    int idx = i4 * 4;
    int c = (idx / P_) % C_;
    float m = g_stats[128 + c], is = g_stats[192 + c];
    float ga = gamma2[c], be = beta2[c];
    float4 v = *(const float4*)&g_y3[idx];
    float4 xr = *(const float4*)&x[idx];
    float4 o;
    o.x = fmaxf((v.x - m) * is * ga + be + xr.x, 0.f);
    o.y = fmaxf((v.y - m) * is * ga + be + xr.y, 0.f);
    o.z = fmaxf((v.z - m) * is * ga + be + xr.z, 0.f);
    o.w = fmaxf((v.w - m) * is * ga + be + xr.w, 0.f);
    *(float4*)&out[idx] = o;
}

// ---------------- launcher ----------------
extern "C" void kernel_launch(void* const* d_in, const int* in_sizes, int n_in,
                              void* d_out, int out_size) {
    const float* x      = (const float*)d_in[0];
    const float* w_off  = (const float*)d_in[1];
    const float* b_off  = (const float*)d_in[2];
    const float* w1     = (const float*)d_in[3];
    const float* gamma1 = (const float*)d_in[4];
    const float* beta1  = (const float*)d_in[5];
    const float* w2     = (const float*)d_in[6];
    const float* b2     = (const float*)d_in[7];
    const float* gamma2 = (const float*)d_in[8];
    const float* beta2  = (const float*)d_in[9];
    float* out = (float*)d_out;

    int padtot = N_*C_*PPAD_;
    int tot4 = N_*C_*P_/4;

    prep_kernel<<<(PREP_TOT + 255) / 256, 256>>>(w_off, w1, w2);
    padinit_kernel<<<(padtot + 255) / 256, 256>>>(x);
    transpose_kernel<<<(N_*G_*P_ + 255) / 256, 256>>>(x);
    offconv_mma_kernel<<<dim3(224, 11), 256>>>(b_off);
    deform_gather_kernel<<<N_*G_*K_*98, 256>>>();
    deform_gemm_kernel<<<448, 128>>>();
    bnstats_kernel<<<64, 256>>>(0);
    bnrelu_kernel<<<(tot4 + 255) / 256, 256>>>(gamma1, beta1);
    conv2_mma_kernel<<<224, 256>>>(b2);
    bnstats_kernel<<<64, 256>>>(1);
    final_kernel<<<(tot4 + 255) / 256, 256>>>(x, gamma2, beta2, out);
}